// round 11
// baseline (speedup 1.0000x reference)
#include <cuda_runtime.h>
#include <cuda_fp16.h>
#include <cstdint>
#include <math.h>

#define EPSV 1e-5f
#define BATCH 16
#define CLSN 20
#define CDIM 768
#define NHEADS 4
#define DHEAD 192
#define NP 1024
#define ROWS (BATCH*CLSN)
#define PPB (CDIM*NP)
#define KPAD 192
#define HALF_B (BATCH/2)

// ---------------- scratch ----------------------------------------------------
__device__ float g_xln[ROWS*CDIM];
__device__ float g_q[ROWS*CDIM];
__device__ float g_sums[32];
__device__ float g_attn[BATCH*NHEADS*CLSN*NP];
__device__ float g_outflat[ROWS*CDIM];
__device__ float g_opatch[BATCH*CLSN*NP];
__device__ float g_alpha[CDIM];
__device__ float g_beta[CDIM];
__device__ __align__(128) __half g_kvh[BATCH*2*CDIM*NP];  // 50 MB fp16
__device__ __align__(128) __half g_Wkvh[2*CDIM*CDIM];
__device__ __align__(128) __half g_nxTh[BATCH*NP*CDIM];   // [b][n][c]
__device__ __align__(128) __half g_W2h[CDIM*KPAD];
__device__ __align__(128) __half g_ich[BATCH*NP*KPAD];    // [b][n][k]

__device__ __forceinline__ float gelu_exact(float x) {
    return 0.5f * x * (1.0f + erff(x * 0.70710678118654752440f));
}
__device__ __forceinline__ uint32_t s2u(const void* p) {
    uint32_t a;
    asm("{ .reg .u64 t; cvta.to.shared.u64 t, %1; cvt.u32.u64 %0, t; }" : "=r"(a) : "l"(p));
    return a;
}
__device__ __forceinline__ void cp16(uint32_t dst, const void* src) {
    asm volatile("cp.async.cg.shared.global [%0], [%1], 16;" :: "r"(dst), "l"(src));
}
#define CP_COMMIT() asm volatile("cp.async.commit_group;" ::: "memory")
#define LDSM_X4(r0,r1,r2,r3,a) \
    asm volatile("ldmatrix.sync.aligned.m8n8.x4.shared.b16 {%0,%1,%2,%3}, [%4];" \
                 : "=r"(r0), "=r"(r1), "=r"(r2), "=r"(r3) : "r"(a))
#define MMA16816(c, a, b0, b1) \
    asm volatile("mma.sync.aligned.m16n8k16.row.col.f32.f16.f16.f32 " \
                 "{%0,%1,%2,%3}, {%4,%5,%6,%7}, {%8,%9}, {%0,%1,%2,%3};" \
                 : "+f"((c)[0]), "+f"((c)[1]), "+f"((c)[2]), "+f"((c)[3]) \
                 : "r"((a)[0]), "r"((a)[1]), "r"((a)[2]), "r"((a)[3]), "r"(b0), "r"(b1))

// ---------------- zero all atomic targets ------------------------------------
__global__ void k_zero(float* __restrict__ out_cls) {
    int i = blockIdx.x * 256 + threadIdx.x;
    if (i < ROWS*CDIM) { g_outflat[i] = 0.0f; g_q[i] = 0.0f; out_cls[i] = 0.0f; }
    if (i < BATCH*CLSN*NP) g_opatch[i] = 0.0f;
    if (i < 32) g_sums[i] = 0.0f;
}

__global__ void k_lncls(const float* __restrict__ x, const float* __restrict__ w,
                        const float* __restrict__ bb) {
    int r = blockIdx.x, tid = threadIdx.x;
    const float* xr = x + r * CDIM;
    float v0 = xr[tid], v1 = xr[tid+256], v2 = xr[tid+512];
    __shared__ float red[256];
    __shared__ float s_mu, s_rs;
    red[tid] = v0 + v1 + v2; __syncthreads();
    for (int o = 128; o; o >>= 1) { if (tid < o) red[tid] += red[tid+o]; __syncthreads(); }
    if (tid == 0) s_mu = red[0] * (1.0f/768.0f);
    __syncthreads();
    float mu = s_mu;
    float d0 = v0-mu, d1 = v1-mu, d2 = v2-mu;
    red[tid] = d0*d0 + d1*d1 + d2*d2; __syncthreads();
    for (int o = 128; o; o >>= 1) { if (tid < o) red[tid] += red[tid+o]; __syncthreads(); }
    if (tid == 0) s_rs = rsqrtf(red[0] * (1.0f/768.0f) + EPSV);
    __syncthreads();
    float rs = s_rs;
    float* o = g_xln + r * CDIM;
    o[tid]     = d0*rs*w[tid]     + bb[tid];
    o[tid+256] = d1*rs*w[tid+256] + bb[tid+256];
    o[tid+512] = d2*rs*w[tid+512] + bb[tid+512];
}

__global__ void k_psum(const float* __restrict__ x) {
    int b = blockIdx.y, tid = threadIdx.x;
    const float* p = x + (size_t)b * PPB + blockIdx.x * 16384 + tid;
    float s = 0.0f, q = 0.0f;
    #pragma unroll 8
    for (int i = 0; i < 64; i++) { float v = p[i*256]; s += v; q += v*v; }
    __shared__ float rs[256], rq[256];
    rs[tid] = s; rq[tid] = q; __syncthreads();
    for (int o = 128; o; o >>= 1) {
        if (tid < o) { rs[tid] += rs[tid+o]; rq[tid] += rq[tid+o]; }
        __syncthreads();
    }
    if (tid == 0) { atomicAdd(&g_sums[b], rs[0]); atomicAdd(&g_sums[16+b], rq[0]); }
}

// normalize + transpose + fp16:  g_nxTh[b][n][c]   (b = blockIdx.z + b0)
__global__ void __launch_bounds__(256) k_nxT(const float* __restrict__ x,
                                             const float* __restrict__ w,
                                             const float* __restrict__ bb, int b0) {
    __shared__ float t[32][33];
    int b = blockIdx.z + b0, c0 = blockIdx.y*32, n0 = blockIdx.x*32;
    int tx = threadIdx.x & 31, ty = threadIdx.x >> 5;
    float mu  = g_sums[b]    * (1.0f/786432.0f);
    float var = g_sums[16+b] * (1.0f/786432.0f) - mu*mu;
    float rv = rsqrtf(var + EPSV);
    #pragma unroll
    for (int i = 0; i < 4; i++) {
        int c = c0 + ty + i*8;
        float v = x[(size_t)b*PPB + (size_t)c*NP + n0 + tx];
        t[tx][ty + i*8] = (v - mu)*rv*w[c] + bb[c];
    }
    __syncthreads();
    #pragma unroll
    for (int i = 0; i < 4; i++) {
        int n = n0 + ty + i*8;
        float v = t[ty + i*8][tx];
        g_nxTh[((size_t)b*NP + n)*CDIM + c0 + tx] = __float2half_rn(v);
    }
}

__global__ void k_prep_wkv(const float* __restrict__ W) {
    int i = blockIdx.x * 256 + threadIdx.x;
    if (i < 2*CDIM*CDIM) g_Wkvh[i] = __float2half_rn(W[i]);
}

__global__ void k_prepconv(const float* __restrict__ Wc, const float* __restrict__ bc,
                           const float* __restrict__ g,  const float* __restrict__ bt,
                           const float* __restrict__ mn, const float* __restrict__ vr) {
    int i = blockIdx.x * 256 + threadIdx.x;
    if (i < CDIM*KPAD) {
        int o = i / KPAD, k = i - o*KPAD;
        g_W2h[i] = __float2half_rn((k < 180) ? Wc[o*180 + k] : 0.0f);
    }
    if (i < CDIM) {
        float al = g[i] * rsqrtf(vr[i] + EPSV);
        g_alpha[i] = al;
        g_beta[i]  = (bc[i] - mn[i]) * al + bt[i];
    }
}

// ---------------- small NT GEMM, split-K x2 (q proj / out proj) --------------
template<int MODE>
__global__ void __launch_bounds__(256) gemm_nt(const float* __restrict__ Bw,
                                               const float* __restrict__ bias,
                                               const float* __restrict__ res,
                                               float* __restrict__ Cext) {
    const float* A = (MODE == 0) ? g_xln : g_outflat;
    float* C = (MODE == 0) ? g_q : Cext;
    __shared__ float As[16*68];
    __shared__ float Bs[16*68];
    int m0 = blockIdx.y * 64, n0 = blockIdx.x * 64, kz = blockIdx.z;
    int tid = threadIdx.x, tx = tid & 15, ty = tid >> 4;
    float acc[4][4] = {};
    int row = tid >> 2, kq = tid & 3;
    for (int k0 = kz*384; k0 < kz*384 + 384; k0 += 16) {
        float4 va = *(const float4*)(A  + (m0+row)*768 + k0 + kq*4);
        float4 vb = *(const float4*)(Bw + (n0+row)*768 + k0 + kq*4);
        As[(kq*4+0)*68+row] = va.x; As[(kq*4+1)*68+row] = va.y;
        As[(kq*4+2)*68+row] = va.z; As[(kq*4+3)*68+row] = va.w;
        Bs[(kq*4+0)*68+row] = vb.x; Bs[(kq*4+1)*68+row] = vb.y;
        Bs[(kq*4+2)*68+row] = vb.z; Bs[(kq*4+3)*68+row] = vb.w;
        __syncthreads();
        #pragma unroll
        for (int k = 0; k < 16; k++) {
            float4 a4 = *(const float4*)(&As[k*68 + ty*4]);
            float4 b4 = *(const float4*)(&Bs[k*68 + tx*4]);
            float am[4] = {a4.x, a4.y, a4.z, a4.w};
            float bn[4] = {b4.x, b4.y, b4.z, b4.w};
            #pragma unroll
            for (int i = 0; i < 4; i++)
                #pragma unroll
                for (int j = 0; j < 4; j++) acc[i][j] += am[i]*bn[j];
        }
        __syncthreads();
    }
    #pragma unroll
    for (int i = 0; i < 4; i++) {
        int m = m0 + ty*4 + i;
        #pragma unroll
        for (int j = 0; j < 4; j++) {
            int n = n0 + tx*4 + j;
            float add = 0.0f;
            if (kz == 0) {
                add = bias[n];
                if (MODE == 1) add += res[m*768 + n];
            }
            atomicAdd(&C[m*768 + n], acc[i][j] + add);
        }
    }
}

// ---------------- mma.sync fp16 GEMM, k32 slabs ------------------------------
// MODE 0 (kv): C fp16 g_kvh[b], +bias.  MODE 1 (conv): C fp32, gelu(al*x+be).
#define TPITCH 80
#define TBYTES (128*TPITCH)
#define STAGEB (2*TBYTES)
#define NSTG 3
#define SMEMB (NSTG*STAGEB)          /* 61440 */
template<int MODE>
__global__ void __launch_bounds__(256, 2) gemm_mma(const float* __restrict__ bias,
                                                   float* __restrict__ Cout, int b0) {
    const int K  = (MODE == 0) ? 768 : KPAD;
    const int NS = K / 32;
    extern __shared__ __align__(1024) char sm[];
    uint32_t sb = s2u(sm);
    int tid = threadIdx.x;
    int w = tid >> 5, l = tid & 31;
    int wm = w >> 1, wn = w & 1;
    int b = blockIdx.z + b0;
    int m0 = blockIdx.y * 128, n0 = blockIdx.x * 128;

    const __half* Ah = (MODE == 0) ? g_Wkvh : g_W2h;
    const __half* Bh = ((MODE == 0) ? g_nxTh : g_ich) + (size_t)b * NP * K;
    __half* Ch = g_kvh + (size_t)b * 2*CDIM*NP;
    float* Cf  = Cout + (size_t)b * CDIM*NP;

    float acc[2][8][4] = {};

    int r0 = tid >> 2, q0 = tid & 3;
    int r1 = ((tid + 256) >> 2), q1 = q0;

    auto load_stage = [&](int s) {
        uint32_t st = sb + (s % NSTG) * STAGEB;
        int k0 = s * 32;
        cp16(st + r0*TPITCH + q0*16,          Ah + (size_t)(m0+r0)*K + k0 + q0*8);
        cp16(st + r1*TPITCH + q1*16,          Ah + (size_t)(m0+r1)*K + k0 + q1*8);
        cp16(st + TBYTES + r0*TPITCH + q0*16, Bh + (size_t)(n0+r0)*K + k0 + q0*8);
        cp16(st + TBYTES + r1*TPITCH + q1*16, Bh + (size_t)(n0+r1)*K + k0 + q1*8);
        CP_COMMIT();
    };
    load_stage(0);
    load_stage(1);

    int lrow = (l & 7) + ((l >> 3) & 1) * 8;
    int lko  = (l >> 4) * 16;

    for (int s = 0; s < NS; s++) {
        if (s + 1 < NS) asm volatile("cp.async.wait_group 1;" ::: "memory");
        else            asm volatile("cp.async.wait_group 0;" ::: "memory");
        __syncthreads();
        if (s + 2 < NS) load_stage(s + 2);
        uint32_t st = sb + (s % NSTG) * STAGEB;
        #pragma unroll
        for (int kk = 0; kk < 2; kk++) {
            uint32_t aro = st + (wm*32 + lrow)*TPITCH + lko + kk*32;
            uint32_t bro = st + TBYTES + (wn*64 + lrow)*TPITCH + lko + kk*32;
            uint32_t ah[2][4], bf[4][4];
            #pragma unroll
            for (int mi = 0; mi < 2; mi++)
                LDSM_X4(ah[mi][0], ah[mi][1], ah[mi][2], ah[mi][3], aro + mi*16*TPITCH);
            #pragma unroll
            for (int np = 0; np < 4; np++)
                LDSM_X4(bf[np][0], bf[np][1], bf[np][2], bf[np][3], bro + np*16*TPITCH);
            #pragma unroll
            for (int mi = 0; mi < 2; mi++)
                #pragma unroll
                for (int ni = 0; ni < 8; ni++) {
                    int np = ni >> 1;
                    uint32_t b0r = (ni & 1) ? bf[np][1] : bf[np][0];
                    uint32_t b1r = (ni & 1) ? bf[np][3] : bf[np][2];
                    MMA16816(acc[mi][ni], ah[mi], b0r, b1r);
                }
        }
    }

    // epilogue
    #pragma unroll
    for (int mi = 0; mi < 2; mi++) {
        int rA = m0 + wm*32 + mi*16 + (l >> 2);
        int rB = rA + 8;
        float pA0, pA1, pB0, pB1;
        if (MODE == 0) { pA0 = bias[rA]; pA1 = 0.0f; pB0 = bias[rB]; pB1 = 0.0f; }
        else { pA0 = g_alpha[rA]; pA1 = g_beta[rA]; pB0 = g_alpha[rB]; pB1 = g_beta[rB]; }
        #pragma unroll
        for (int ni = 0; ni < 8; ni++) {
            int col = n0 + wn*64 + ni*8 + (l & 3)*2;
            float* c = acc[mi][ni];
            if (MODE == 0) {
                *(__half2*)(Ch + (size_t)rA*NP + col) = __floats2half2_rn(c[0]+pA0, c[1]+pA0);
                *(__half2*)(Ch + (size_t)rB*NP + col) = __floats2half2_rn(c[2]+pB0, c[3]+pB0);
            } else {
                *(float2*)(Cf + (size_t)rA*NP + col) =
                    make_float2(gelu_exact(c[0]*pA0 + pA1), gelu_exact(c[1]*pA0 + pA1));
                *(float2*)(Cf + (size_t)rB*NP + col) =
                    make_float2(gelu_exact(c[2]*pB0 + pB1), gelu_exact(c[3]*pB0 + pB1));
            }
        }
    }
}

// ---------------- attention (3 kernels, per-half) ----------------------------
__global__ void __launch_bounds__(256) k_logits(int b0) {
    int chunk = blockIdx.x, h = blockIdx.y, b = blockIdx.z + b0;
    int tid = threadIdx.x;
    __shared__ float qs[CLSN*DHEAD];
    const float scale = 0.07216878364870322f;
    for (int i = tid; i < CLSN*DHEAD; i += 256) {
        int m = i / DHEAD, d = i - m*DHEAD;
        qs[i] = g_q[(b*CLSN + m)*CDIM + h*DHEAD + d] * scale;
    }
    __syncthreads();
    int n = chunk*256 + tid;
    const __half* kvp = g_kvh + ((size_t)b*2*CDIM + h*DHEAD)*NP + n;
    float acc[CLSN] = {};
    for (int d = 0; d < DHEAD; d++) {
        float kval = __half2float(kvp[(size_t)d * NP]);
        #pragma unroll
        for (int m = 0; m < CLSN; m++) acc[m] += qs[m*DHEAD + d] * kval;
    }
    float* ap = g_attn + (((size_t)(b*NHEADS + h))*CLSN)*NP + n;
    #pragma unroll
    for (int m = 0; m < CLSN; m++) ap[(size_t)m*NP] = acc[m];
}

__global__ void k_softmax(int row0) {
    int row = blockIdx.x + row0, tid = threadIdx.x;
    float* p = g_attn + (size_t)row * NP;
    float v[4];
    #pragma unroll
    for (int i = 0; i < 4; i++) v[i] = p[tid + i*256];
    float mx = fmaxf(fmaxf(v[0],v[1]), fmaxf(v[2],v[3]));
    __shared__ float red[256];
    red[tid] = mx; __syncthreads();
    for (int o = 128; o; o >>= 1) { if (tid < o) red[tid] = fmaxf(red[tid], red[tid+o]); __syncthreads(); }
    mx = red[0]; __syncthreads();
    float s = 0.0f;
    #pragma unroll
    for (int i = 0; i < 4; i++) { v[i] = __expf(v[i] - mx); s += v[i]; }
    red[tid] = s; __syncthreads();
    for (int o = 128; o; o >>= 1) { if (tid < o) red[tid] += red[tid+o]; __syncthreads(); }
    float inv = 1.0f / red[0];
    #pragma unroll
    for (int i = 0; i < 4; i++) p[tid + i*256] = v[i] * inv;
}

__global__ void __launch_bounds__(192) k_out(int b0) {
    int chunk = blockIdx.x, h = blockIdx.y, b = blockIdx.z + b0;
    int tid = threadIdx.x;
    __shared__ float attn_s[CLSN*256];
    for (int i = tid; i < CLSN*256; i += 192) {
        int m = i >> 8, nn = i & 255;
        attn_s[i] = g_attn[(((size_t)(b*NHEADS + h))*CLSN + m)*NP + chunk*256 + nn];
    }
    __syncthreads();
    const __half* vp = g_kvh + ((size_t)b*2*CDIM + CDIM + h*DHEAD + tid)*NP + chunk*256;
    float acc[CLSN] = {};
    for (int nn = 0; nn < 256; nn += 2) {
        float2 vv = __half22float2(*(const __half2*)(vp + nn));
        #pragma unroll
        for (int m = 0; m < CLSN; m++)
            acc[m] += attn_s[m*256 + nn]*vv.x + attn_s[m*256 + nn + 1]*vv.y;
    }
    #pragma unroll
    for (int m = 0; m < CLSN; m++)
        atomicAdd(&g_outflat[(b*CLSN + m)*CDIM + h*DHEAD + tid], acc[m]);
}

// ---------------- out_patch = out_cls @ input_patch, split-K x2 --------------
__global__ void __launch_bounds__(256) k_opatch(const float* __restrict__ patch,
                                                const float* __restrict__ ocls) {
    int chunk = blockIdx.x, b = blockIdx.y, kz = blockIdx.z;
    int tid = threadIdx.x;
    int n = chunk*256 + tid;
    __shared__ float a_s[CLSN*96];
    float acc[CLSN] = {};
    for (int k0 = kz*384; k0 < kz*384 + 384; k0 += 96) {
        __syncthreads();
        for (int i = tid; i < CLSN*96; i += 256) {
            int m = i / 96, kk = i - m*96;
            a_s[i] = ocls[(b*CLSN + m)*CDIM + k0 + kk];
        }
        __syncthreads();
        for (int kk = 0; kk < 96; kk++) {
            float pv = patch[(size_t)b*PPB + (size_t)(k0+kk)*NP + n];
            #pragma unroll
            for (int m = 0; m < CLSN; m++) acc[m] += a_s[m*96 + kk] * pv;
        }
    }
    #pragma unroll
    for (int m = 0; m < CLSN; m++)
        atomicAdd(&g_opatch[((size_t)b*CLSN + m)*NP + n], acc[m]);
}

// ---------------- im2col transposed + fp16 -----------------------------------
__global__ void k_im2colT() {
    int i = blockIdx.x * 256 + threadIdx.x;
    int b = i / (NP*KPAD);
    int rest = i - b * NP*KPAD;
    int n = rest / KPAD, k = rest - n*KPAD;
    float val = 0.0f;
    if (k < 180) {
        int ic = k / 9, t = k - ic*9;
        int hh = (n >> 5) + t/3 - 1, ww = (n & 31) + t%3 - 1;
        if (hh >= 0 && hh < 32 && ww >= 0 && ww < 32)
            val = g_opatch[((size_t)b*CLSN + ic)*NP + hh*32 + ww];
    }
    g_ich[i] = __float2half_rn(val);
}

// ---------------- launcher ---------------------------------------------------
extern "C" void kernel_launch(void* const* d_in, const int* in_sizes, int n_in,
                              void* d_out, int out_size) {
    const float* x_cls  = (const float*)d_in[0];
    const float* patch  = (const float*)d_in[1];
    const float* ln_w   = (const float*)d_in[2];
    const float* ln_b   = (const float*)d_in[3];
    const float* nx_w   = (const float*)d_in[4];
    const float* nx_b   = (const float*)d_in[5];
    const float* Wq     = (const float*)d_in[6];
    const float* bq     = (const float*)d_in[7];
    const float* Wkv    = (const float*)d_in[8];
    const float* bkv    = (const float*)d_in[9];
    const float* Wp     = (const float*)d_in[10];
    const float* bp     = (const float*)d_in[11];
    const float* Wconv  = (const float*)d_in[12];
    const float* bconv  = (const float*)d_in[13];
    const float* bn_g   = (const float*)d_in[14];
    const float* bn_b   = (const float*)d_in[15];
    const float* bn_m   = (const float*)d_in[16];
    const float* bn_v   = (const float*)d_in[17];
    float* out_cls = (float*)d_out;
    float* y       = out_cls + ROWS*CDIM;

    static cudaStream_t s1 = nullptr, s2 = nullptr, s3 = nullptr;
    static cudaEvent_t e0, e1, e2, e3, eP, eB;
    if (!s1) {
        cudaStreamCreateWithFlags(&s1, cudaStreamNonBlocking);
        cudaStreamCreateWithFlags(&s2, cudaStreamNonBlocking);
        cudaStreamCreateWithFlags(&s3, cudaStreamNonBlocking);
        cudaEventCreateWithFlags(&e0, cudaEventDisableTiming);
        cudaEventCreateWithFlags(&e1, cudaEventDisableTiming);
        cudaEventCreateWithFlags(&e2, cudaEventDisableTiming);
        cudaEventCreateWithFlags(&e3, cudaEventDisableTiming);
        cudaEventCreateWithFlags(&eP, cudaEventDisableTiming);
        cudaEventCreateWithFlags(&eB, cudaEventDisableTiming);
        cudaFuncSetAttribute(gemm_mma<0>, cudaFuncAttributeMaxDynamicSharedMemorySize, SMEMB);
        cudaFuncSetAttribute(gemm_mma<1>, cudaFuncAttributeMaxDynamicSharedMemorySize, SMEMB);
    }
    cudaStream_t s0 = 0;

    // ---- fork point ----
    k_zero<<<1280, 256, 0, s0>>>(out_cls);
    cudaEventRecord(e0, s0);

    // side chain 1: cls LN + q projection
    cudaStreamWaitEvent(s1, e0, 0);
    k_lncls<<<ROWS, 256, 0, s1>>>(x_cls, ln_w, ln_b);
    gemm_nt<0><<<dim3(12, 5, 2), 256, 0, s1>>>(Wq, bq, nullptr, nullptr);
    cudaEventRecord(e1, s1);

    // side chain 2: weight preps
    cudaStreamWaitEvent(s2, e0, 0);
    k_prep_wkv<<<(2*CDIM*CDIM)/256, 256, 0, s2>>>(Wkv);
    cudaEventRecord(e2, s2);
    k_prepconv<<<(CDIM*KPAD + 255)/256, 256, 0, s2>>>(Wconv, bconv, bn_g, bn_b, bn_m, bn_v);
    cudaEventRecord(e3, s2);

    // main: psum (both halves need it)
    k_psum<<<dim3(48, BATCH), 256, 0, s0>>>(patch);
    cudaEventRecord(eP, s0);

    // ---- half A (b 0-7) on s0 ----
    k_nxT<<<dim3(32, 24, HALF_B), 256, 0, s0>>>(patch, nx_w, nx_b, 0);
    cudaStreamWaitEvent(s0, e2, 0);
    gemm_mma<0><<<dim3(8, 12, HALF_B), 256, SMEMB, s0>>>(bkv, nullptr, 0);
    cudaStreamWaitEvent(s0, e1, 0);
    k_logits<<<dim3(4, NHEADS, HALF_B), 256, 0, s0>>>(0);
    k_softmax<<<HALF_B*NHEADS*CLSN, 256, 0, s0>>>(0);
    k_out<<<dim3(4, NHEADS, HALF_B), 192, 0, s0>>>(0);

    // ---- half B (b 8-15) on s3 ----
    cudaStreamWaitEvent(s3, eP, 0);
    k_nxT<<<dim3(32, 24, HALF_B), 256, 0, s3>>>(patch, nx_w, nx_b, HALF_B);
    cudaStreamWaitEvent(s3, e2, 0);
    gemm_mma<0><<<dim3(8, 12, HALF_B), 256, SMEMB, s3>>>(bkv, nullptr, HALF_B);
    cudaStreamWaitEvent(s3, e1, 0);
    k_logits<<<dim3(4, NHEADS, HALF_B), 256, 0, s3>>>(HALF_B);
    k_softmax<<<HALF_B*NHEADS*CLSN, 256, 0, s3>>>(HALF_B*NHEADS*CLSN);
    k_out<<<dim3(4, NHEADS, HALF_B), 192, 0, s3>>>(HALF_B);
    cudaEventRecord(eB, s3);

    // ---- join: tail chain on s0 ----
    cudaStreamWaitEvent(s0, eB, 0);
    gemm_nt<1><<<dim3(12, 5, 2), 256, 0, s0>>>(Wp, bp, x_cls, out_cls);
    k_opatch<<<dim3(4, BATCH, 2), 256, 0, s0>>>(patch, out_cls);
    k_im2colT<<<(BATCH*NP*KPAD)/256, 256, 0, s0>>>();
    cudaStreamWaitEvent(s0, e3, 0);
    gemm_mma<1><<<dim3(8, 6, BATCH), 256, SMEMB, s0>>>(nullptr, y, 0);
}

// round 12
// speedup vs baseline: 1.0482x; 1.0482x over previous
#include <cuda_runtime.h>
#include <cuda_fp16.h>
#include <cstdint>
#include <math.h>

#define EPSV 1e-5f
#define BATCH 16
#define CLSN 20
#define CDIM 768
#define NHEADS 4
#define DHEAD 192
#define NP 1024
#define ROWS (BATCH*CLSN)
#define PPB (CDIM*NP)
#define KPAD 192

// ---------------- scratch ----------------------------------------------------
__device__ float g_xln[ROWS*CDIM];
__device__ float g_q[ROWS*CDIM];
__device__ float g_sums[32];
__device__ float g_attn[BATCH*NHEADS*CLSN*NP];
__device__ float g_rowsum[BATCH*NHEADS*CLSN];
__device__ float g_outflat[ROWS*CDIM];
__device__ float g_opatch[BATCH*CLSN*NP];
__device__ float g_alpha[CDIM];
__device__ float g_beta[CDIM];
__device__ __align__(128) __half g_kvh[BATCH*2*CDIM*NP];  // 50 MB fp16
__device__ __align__(128) __half g_Wkvh[2*CDIM*CDIM];
__device__ __align__(128) __half g_nxTh[BATCH*NP*CDIM];   // [b][n][c]
__device__ __align__(128) __half g_W2h[CDIM*KPAD];
__device__ __align__(128) __half g_ich[BATCH*NP*KPAD];    // [b][n][k]

__device__ __forceinline__ float gelu_exact(float x) {
    return 0.5f * x * (1.0f + erff(x * 0.70710678118654752440f));
}
__device__ __forceinline__ uint32_t s2u(const void* p) {
    uint32_t a;
    asm("{ .reg .u64 t; cvta.to.shared.u64 t, %1; cvt.u32.u64 %0, t; }" : "=r"(a) : "l"(p));
    return a;
}
__device__ __forceinline__ void cp16(uint32_t dst, const void* src) {
    asm volatile("cp.async.cg.shared.global [%0], [%1], 16;" :: "r"(dst), "l"(src));
}
#define CP_COMMIT() asm volatile("cp.async.commit_group;" ::: "memory")
#define LDSM_X4(r0,r1,r2,r3,a) \
    asm volatile("ldmatrix.sync.aligned.m8n8.x4.shared.b16 {%0,%1,%2,%3}, [%4];" \
                 : "=r"(r0), "=r"(r1), "=r"(r2), "=r"(r3) : "r"(a))
#define MMA16816(c, a, b0, b1) \
    asm volatile("mma.sync.aligned.m16n8k16.row.col.f32.f16.f16.f32 " \
                 "{%0,%1,%2,%3}, {%4,%5,%6,%7}, {%8,%9}, {%0,%1,%2,%3};" \
                 : "+f"((c)[0]), "+f"((c)[1]), "+f"((c)[2]), "+f"((c)[3]) \
                 : "r"((a)[0]), "r"((a)[1]), "r"((a)[2]), "r"((a)[3]), "r"(b0), "r"(b1))

// ---------------- zero all atomic targets ------------------------------------
__global__ void k_zero(float* __restrict__ out_cls) {
    int i = blockIdx.x * 256 + threadIdx.x;
    if (i < ROWS*CDIM) { g_outflat[i] = 0.0f; g_q[i] = 0.0f; out_cls[i] = 0.0f; }
    if (i < BATCH*CLSN*NP) g_opatch[i] = 0.0f;
    if (i < BATCH*NHEADS*CLSN) g_rowsum[i] = 0.0f;
    if (i < 32) g_sums[i] = 0.0f;
}

__global__ void k_lncls(const float* __restrict__ x, const float* __restrict__ w,
                        const float* __restrict__ bb) {
    int r = blockIdx.x, tid = threadIdx.x;
    const float* xr = x + r * CDIM;
    float v0 = xr[tid], v1 = xr[tid+256], v2 = xr[tid+512];
    __shared__ float red[256];
    __shared__ float s_mu, s_rs;
    red[tid] = v0 + v1 + v2; __syncthreads();
    for (int o = 128; o; o >>= 1) { if (tid < o) red[tid] += red[tid+o]; __syncthreads(); }
    if (tid == 0) s_mu = red[0] * (1.0f/768.0f);
    __syncthreads();
    float mu = s_mu;
    float d0 = v0-mu, d1 = v1-mu, d2 = v2-mu;
    red[tid] = d0*d0 + d1*d1 + d2*d2; __syncthreads();
    for (int o = 128; o; o >>= 1) { if (tid < o) red[tid] += red[tid+o]; __syncthreads(); }
    if (tid == 0) s_rs = rsqrtf(red[0] * (1.0f/768.0f) + EPSV);
    __syncthreads();
    float rs = s_rs;
    float* o = g_xln + r * CDIM;
    o[tid]     = d0*rs*w[tid]     + bb[tid];
    o[tid+256] = d1*rs*w[tid+256] + bb[tid+256];
    o[tid+512] = d2*rs*w[tid+512] + bb[tid+512];
}

__global__ void k_psum(const float* __restrict__ x) {
    int b = blockIdx.y, tid = threadIdx.x;
    const float* p = x + (size_t)b * PPB + blockIdx.x * 16384 + tid;
    float s = 0.0f, q = 0.0f;
    #pragma unroll 8
    for (int i = 0; i < 64; i++) { float v = p[i*256]; s += v; q += v*v; }
    __shared__ float rs[256], rq[256];
    rs[tid] = s; rq[tid] = q; __syncthreads();
    for (int o = 128; o; o >>= 1) {
        if (tid < o) { rs[tid] += rs[tid+o]; rq[tid] += rq[tid+o]; }
        __syncthreads();
    }
    if (tid == 0) { atomicAdd(&g_sums[b], rs[0]); atomicAdd(&g_sums[16+b], rq[0]); }
}

// normalize + transpose + fp16:  g_nxTh[b][n][c]
__global__ void __launch_bounds__(256) k_nxT(const float* __restrict__ x,
                                             const float* __restrict__ w,
                                             const float* __restrict__ bb) {
    __shared__ float t[32][33];
    int b = blockIdx.z, c0 = blockIdx.y*32, n0 = blockIdx.x*32;
    int tx = threadIdx.x & 31, ty = threadIdx.x >> 5;
    float mu  = g_sums[b]    * (1.0f/786432.0f);
    float var = g_sums[16+b] * (1.0f/786432.0f) - mu*mu;
    float rv = rsqrtf(var + EPSV);
    #pragma unroll
    for (int i = 0; i < 4; i++) {
        int c = c0 + ty + i*8;
        float v = x[(size_t)b*PPB + (size_t)c*NP + n0 + tx];
        t[tx][ty + i*8] = (v - mu)*rv*w[c] + bb[c];
    }
    __syncthreads();
    #pragma unroll
    for (int i = 0; i < 4; i++) {
        int n = n0 + ty + i*8;
        float v = t[ty + i*8][tx];
        g_nxTh[((size_t)b*NP + n)*CDIM + c0 + tx] = __float2half_rn(v);
    }
}

__global__ void k_prep_wkv(const float* __restrict__ W) {
    int i = blockIdx.x * 256 + threadIdx.x;
    if (i < 2*CDIM*CDIM) g_Wkvh[i] = __float2half_rn(W[i]);
}

__global__ void k_prepconv(const float* __restrict__ Wc, const float* __restrict__ bc,
                           const float* __restrict__ g,  const float* __restrict__ bt,
                           const float* __restrict__ mn, const float* __restrict__ vr) {
    int i = blockIdx.x * 256 + threadIdx.x;
    if (i < CDIM*KPAD) {
        int o = i / KPAD, k = i - o*KPAD;
        g_W2h[i] = __float2half_rn((k < 180) ? Wc[o*180 + k] : 0.0f);
    }
    if (i < CDIM) {
        float al = g[i] * rsqrtf(vr[i] + EPSV);
        g_alpha[i] = al;
        g_beta[i]  = (bc[i] - mn[i]) * al + bt[i];
    }
}

// ---------------- small NT GEMM, split-K x2 (q proj / out proj) --------------
template<int MODE>
__global__ void __launch_bounds__(256) gemm_nt(const float* __restrict__ Bw,
                                               const float* __restrict__ bias,
                                               const float* __restrict__ res,
                                               float* __restrict__ Cext) {
    const float* A = (MODE == 0) ? g_xln : g_outflat;
    float* C = (MODE == 0) ? g_q : Cext;
    __shared__ float As[16*68];
    __shared__ float Bs[16*68];
    int m0 = blockIdx.y * 64, n0 = blockIdx.x * 64, kz = blockIdx.z;
    int tid = threadIdx.x, tx = tid & 15, ty = tid >> 4;
    float acc[4][4] = {};
    int row = tid >> 2, kq = tid & 3;
    for (int k0 = kz*384; k0 < kz*384 + 384; k0 += 16) {
        float4 va = *(const float4*)(A  + (m0+row)*768 + k0 + kq*4);
        float4 vb = *(const float4*)(Bw + (n0+row)*768 + k0 + kq*4);
        As[(kq*4+0)*68+row] = va.x; As[(kq*4+1)*68+row] = va.y;
        As[(kq*4+2)*68+row] = va.z; As[(kq*4+3)*68+row] = va.w;
        Bs[(kq*4+0)*68+row] = vb.x; Bs[(kq*4+1)*68+row] = vb.y;
        Bs[(kq*4+2)*68+row] = vb.z; Bs[(kq*4+3)*68+row] = vb.w;
        __syncthreads();
        #pragma unroll
        for (int k = 0; k < 16; k++) {
            float4 a4 = *(const float4*)(&As[k*68 + ty*4]);
            float4 b4 = *(const float4*)(&Bs[k*68 + tx*4]);
            float am[4] = {a4.x, a4.y, a4.z, a4.w};
            float bn[4] = {b4.x, b4.y, b4.z, b4.w};
            #pragma unroll
            for (int i = 0; i < 4; i++)
                #pragma unroll
                for (int j = 0; j < 4; j++) acc[i][j] += am[i]*bn[j];
        }
        __syncthreads();
    }
    #pragma unroll
    for (int i = 0; i < 4; i++) {
        int m = m0 + ty*4 + i;
        #pragma unroll
        for (int j = 0; j < 4; j++) {
            int n = n0 + tx*4 + j;
            float add = 0.0f;
            if (kz == 0) {
                add = bias[n];
                if (MODE == 1) add += res[m*768 + n];
            }
            atomicAdd(&C[m*768 + n], acc[i][j] + add);
        }
    }
}

// ---------------- mma.sync fp16 GEMM, k32 slabs ------------------------------
#define TPITCH 80
#define TBYTES (128*TPITCH)
#define STAGEB (2*TBYTES)
#define NSTG 3
#define SMEMB (NSTG*STAGEB)          /* 61440 */
template<int MODE>
__global__ void __launch_bounds__(256, 2) gemm_mma(const float* __restrict__ bias,
                                                   float* __restrict__ Cout) {
    const int K  = (MODE == 0) ? 768 : KPAD;
    const int NS = K / 32;
    extern __shared__ __align__(1024) char sm[];
    uint32_t sb = s2u(sm);
    int tid = threadIdx.x;
    int w = tid >> 5, l = tid & 31;
    int wm = w >> 1, wn = w & 1;
    int b = blockIdx.z;
    int m0 = blockIdx.y * 128, n0 = blockIdx.x * 128;

    const __half* Ah = (MODE == 0) ? g_Wkvh : g_W2h;
    const __half* Bh = ((MODE == 0) ? g_nxTh : g_ich) + (size_t)b * NP * K;
    __half* Ch = g_kvh + (size_t)b * 2*CDIM*NP;
    float* Cf  = Cout + (size_t)b * CDIM*NP;

    float acc[2][8][4] = {};

    int r0 = tid >> 2, q0 = tid & 3;
    int r1 = ((tid + 256) >> 2), q1 = q0;

    auto load_stage = [&](int s) {
        uint32_t st = sb + (s % NSTG) * STAGEB;
        int k0 = s * 32;
        cp16(st + r0*TPITCH + q0*16,          Ah + (size_t)(m0+r0)*K + k0 + q0*8);
        cp16(st + r1*TPITCH + q1*16,          Ah + (size_t)(m0+r1)*K + k0 + q1*8);
        cp16(st + TBYTES + r0*TPITCH + q0*16, Bh + (size_t)(n0+r0)*K + k0 + q0*8);
        cp16(st + TBYTES + r1*TPITCH + q1*16, Bh + (size_t)(n0+r1)*K + k0 + q1*8);
        CP_COMMIT();
    };
    load_stage(0);
    load_stage(1);

    int lrow = (l & 7) + ((l >> 3) & 1) * 8;
    int lko  = (l >> 4) * 16;

    for (int s = 0; s < NS; s++) {
        if (s + 1 < NS) asm volatile("cp.async.wait_group 1;" ::: "memory");
        else            asm volatile("cp.async.wait_group 0;" ::: "memory");
        __syncthreads();
        if (s + 2 < NS) load_stage(s + 2);
        uint32_t st = sb + (s % NSTG) * STAGEB;
        #pragma unroll
        for (int kk = 0; kk < 2; kk++) {
            uint32_t aro = st + (wm*32 + lrow)*TPITCH + lko + kk*32;
            uint32_t bro = st + TBYTES + (wn*64 + lrow)*TPITCH + lko + kk*32;
            uint32_t ah[2][4], bf[4][4];
            #pragma unroll
            for (int mi = 0; mi < 2; mi++)
                LDSM_X4(ah[mi][0], ah[mi][1], ah[mi][2], ah[mi][3], aro + mi*16*TPITCH);
            #pragma unroll
            for (int np = 0; np < 4; np++)
                LDSM_X4(bf[np][0], bf[np][1], bf[np][2], bf[np][3], bro + np*16*TPITCH);
            #pragma unroll
            for (int mi = 0; mi < 2; mi++)
                #pragma unroll
                for (int ni = 0; ni < 8; ni++) {
                    int np = ni >> 1;
                    uint32_t b0r = (ni & 1) ? bf[np][1] : bf[np][0];
                    uint32_t b1r = (ni & 1) ? bf[np][3] : bf[np][2];
                    MMA16816(acc[mi][ni], ah[mi], b0r, b1r);
                }
        }
    }

    // epilogue
    #pragma unroll
    for (int mi = 0; mi < 2; mi++) {
        int rA = m0 + wm*32 + mi*16 + (l >> 2);
        int rB = rA + 8;
        float pA0, pA1, pB0, pB1;
        if (MODE == 0) { pA0 = bias[rA]; pA1 = 0.0f; pB0 = bias[rB]; pB1 = 0.0f; }
        else { pA0 = g_alpha[rA]; pA1 = g_beta[rA]; pB0 = g_alpha[rB]; pB1 = g_beta[rB]; }
        #pragma unroll
        for (int ni = 0; ni < 8; ni++) {
            int col = n0 + wn*64 + ni*8 + (l & 3)*2;
            float* c = acc[mi][ni];
            if (MODE == 0) {
                *(__half2*)(Ch + (size_t)rA*NP + col) = __floats2half2_rn(c[0]+pA0, c[1]+pA0);
                *(__half2*)(Ch + (size_t)rB*NP + col) = __floats2half2_rn(c[2]+pB0, c[3]+pB0);
            } else {
                *(float2*)(Cf + (size_t)rA*NP + col) =
                    make_float2(gelu_exact(c[0]*pA0 + pA1), gelu_exact(c[1]*pA0 + pA1));
                *(float2*)(Cf + (size_t)rB*NP + col) =
                    make_float2(gelu_exact(c[2]*pB0 + pB1), gelu_exact(c[3]*pB0 + pB1));
            }
        }
    }
}

// ---------------- attention: logits+exp+rowsum, then AV+normalize ------------
__global__ void __launch_bounds__(256) k_logits() {
    int chunk = blockIdx.x, h = blockIdx.y, b = blockIdx.z;
    int tid = threadIdx.x, l = tid & 31, w = tid >> 5;
    __shared__ float qs[CLSN*DHEAD];
    __shared__ float bsum[CLSN];
    const float scale = 0.07216878364870322f;   // 1/sqrt(192)
    for (int i = tid; i < CLSN*DHEAD; i += 256) {
        int m = i / DHEAD, d = i - m*DHEAD;
        qs[i] = g_q[(b*CLSN + m)*CDIM + h*DHEAD + d] * scale;
    }
    if (tid < CLSN) bsum[tid] = 0.0f;
    __syncthreads();
    int n = chunk*256 + tid;
    const __half* kvp = g_kvh + ((size_t)b*2*CDIM + h*DHEAD)*NP + n;
    float acc[CLSN] = {};
    for (int d = 0; d < DHEAD; d++) {
        float kval = __half2float(kvp[(size_t)d * NP]);
        #pragma unroll
        for (int m = 0; m < CLSN; m++) acc[m] += qs[m*DHEAD + d] * kval;
    }
    float* ap = g_attn + (((size_t)(b*NHEADS + h))*CLSN)*NP + n;
    #pragma unroll
    for (int m = 0; m < CLSN; m++) {
        float e = __expf(acc[m]);
        ap[(size_t)m*NP] = e;
        #pragma unroll
        for (int o = 16; o; o >>= 1) e += __shfl_xor_sync(0xFFFFFFFFu, e, o);
        if (l == 0) atomicAdd(&bsum[m], e);
    }
    __syncthreads();
    if (tid < CLSN)
        atomicAdd(&g_rowsum[((size_t)(b*NHEADS + h))*CLSN + tid], bsum[tid]);
}

__global__ void __launch_bounds__(192) k_out() {
    int chunk = blockIdx.x, h = blockIdx.y, b = blockIdx.z;
    int tid = threadIdx.x;
    __shared__ float attn_s[CLSN*256];
    __shared__ float inv_s[CLSN];
    for (int i = tid; i < CLSN*256; i += 192) {
        int m = i >> 8, nn = i & 255;
        attn_s[i] = g_attn[(((size_t)(b*NHEADS + h))*CLSN + m)*NP + chunk*256 + nn];
    }
    if (tid < CLSN)
        inv_s[tid] = 1.0f / g_rowsum[((size_t)(b*NHEADS + h))*CLSN + tid];
    __syncthreads();
    const __half* vp = g_kvh + ((size_t)b*2*CDIM + CDIM + h*DHEAD + tid)*NP + chunk*256;
    float acc[CLSN] = {};
    for (int nn = 0; nn < 256; nn += 2) {
        float2 vv = __half22float2(*(const __half2*)(vp + nn));
        #pragma unroll
        for (int m = 0; m < CLSN; m++)
            acc[m] += attn_s[m*256 + nn]*vv.x + attn_s[m*256 + nn + 1]*vv.y;
    }
    #pragma unroll
    for (int m = 0; m < CLSN; m++)
        atomicAdd(&g_outflat[(b*CLSN + m)*CDIM + h*DHEAD + tid], acc[m] * inv_s[m]);
}

// ---------------- out_patch = out_cls @ input_patch, split-K x2 --------------
__global__ void __launch_bounds__(256) k_opatch(const float* __restrict__ patch,
                                                const float* __restrict__ ocls) {
    int chunk = blockIdx.x, b = blockIdx.y, kz = blockIdx.z;
    int tid = threadIdx.x;
    int n = chunk*256 + tid;
    __shared__ float a_s[CLSN*96];
    float acc[CLSN] = {};
    for (int k0 = kz*384; k0 < kz*384 + 384; k0 += 96) {
        __syncthreads();
        for (int i = tid; i < CLSN*96; i += 256) {
            int m = i / 96, kk = i - m*96;
            a_s[i] = ocls[(b*CLSN + m)*CDIM + k0 + kk];
        }
        __syncthreads();
        for (int kk = 0; kk < 96; kk++) {
            float pv = patch[(size_t)b*PPB + (size_t)(k0+kk)*NP + n];
            #pragma unroll
            for (int m = 0; m < CLSN; m++) acc[m] += a_s[m*96 + kk] * pv;
        }
    }
    #pragma unroll
    for (int m = 0; m < CLSN; m++)
        atomicAdd(&g_opatch[((size_t)b*CLSN + m)*NP + n], acc[m]);
}

// ---------------- im2col transposed + fp16 -----------------------------------
__global__ void k_im2colT() {
    int i = blockIdx.x * 256 + threadIdx.x;
    int b = i / (NP*KPAD);
    int rest = i - b * NP*KPAD;
    int n = rest / KPAD, k = rest - n*KPAD;
    float val = 0.0f;
    if (k < 180) {
        int ic = k / 9, t = k - ic*9;
        int hh = (n >> 5) + t/3 - 1, ww = (n & 31) + t%3 - 1;
        if (hh >= 0 && hh < 32 && ww >= 0 && ww < 32)
            val = g_opatch[((size_t)b*CLSN + ic)*NP + hh*32 + ww];
    }
    g_ich[i] = __float2half_rn(val);
}

// ---------------- launcher ---------------------------------------------------
extern "C" void kernel_launch(void* const* d_in, const int* in_sizes, int n_in,
                              void* d_out, int out_size) {
    const float* x_cls  = (const float*)d_in[0];
    const float* patch  = (const float*)d_in[1];
    const float* ln_w   = (const float*)d_in[2];
    const float* ln_b   = (const float*)d_in[3];
    const float* nx_w   = (const float*)d_in[4];
    const float* nx_b   = (const float*)d_in[5];
    const float* Wq     = (const float*)d_in[6];
    const float* bq     = (const float*)d_in[7];
    const float* Wkv    = (const float*)d_in[8];
    const float* bkv    = (const float*)d_in[9];
    const float* Wp     = (const float*)d_in[10];
    const float* bp     = (const float*)d_in[11];
    const float* Wconv  = (const float*)d_in[12];
    const float* bconv  = (const float*)d_in[13];
    const float* bn_g   = (const float*)d_in[14];
    const float* bn_b   = (const float*)d_in[15];
    const float* bn_m   = (const float*)d_in[16];
    const float* bn_v   = (const float*)d_in[17];
    float* out_cls = (float*)d_out;
    float* y       = out_cls + ROWS*CDIM;

    static cudaStream_t s1 = nullptr, s2 = nullptr;
    static cudaEvent_t e0, e1, e2, e3;
    if (!s1) {
        cudaStreamCreateWithFlags(&s1, cudaStreamNonBlocking);
        cudaStreamCreateWithFlags(&s2, cudaStreamNonBlocking);
        cudaEventCreateWithFlags(&e0, cudaEventDisableTiming);
        cudaEventCreateWithFlags(&e1, cudaEventDisableTiming);
        cudaEventCreateWithFlags(&e2, cudaEventDisableTiming);
        cudaEventCreateWithFlags(&e3, cudaEventDisableTiming);
        cudaFuncSetAttribute(gemm_mma<0>, cudaFuncAttributeMaxDynamicSharedMemorySize, SMEMB);
        cudaFuncSetAttribute(gemm_mma<1>, cudaFuncAttributeMaxDynamicSharedMemorySize, SMEMB);
    }
    cudaStream_t s0 = 0;

    // ---- fork point: everything depends on k_zero ----
    k_zero<<<1280, 256, 0, s0>>>(out_cls);
    cudaEventRecord(e0, s0);

    // side chain 1: cls LN + q projection (joined before k_logits)
    cudaStreamWaitEvent(s1, e0, 0);
    k_lncls<<<ROWS, 256, 0, s1>>>(x_cls, ln_w, ln_b);
    gemm_nt<0><<<dim3(12, 5, 2), 256, 0, s1>>>(Wq, bq, nullptr, nullptr);
    cudaEventRecord(e1, s1);

    // side chain 2: weight preps (joined before their consumer GEMMs)
    cudaStreamWaitEvent(s2, e0, 0);
    k_prep_wkv<<<(2*CDIM*CDIM)/256, 256, 0, s2>>>(Wkv);
    cudaEventRecord(e2, s2);
    k_prepconv<<<(CDIM*KPAD + 255)/256, 256, 0, s2>>>(Wconv, bconv, bn_g, bn_b, bn_m, bn_v);
    cudaEventRecord(e3, s2);

    // main chain (critical path)
    k_psum<<<dim3(48, BATCH), 256, 0, s0>>>(patch);
    k_nxT<<<dim3(32, 24, BATCH), 256, 0, s0>>>(patch, nx_w, nx_b);
    cudaStreamWaitEvent(s0, e2, 0);
    gemm_mma<0><<<dim3(8, 12, BATCH), 256, SMEMB, s0>>>(bkv, nullptr);
    cudaStreamWaitEvent(s0, e1, 0);
    k_logits<<<dim3(4, NHEADS, BATCH), 256, 0, s0>>>();
    k_out<<<dim3(4, NHEADS, BATCH), 192, 0, s0>>>();
    gemm_nt<1><<<dim3(12, 5, 2), 256, 0, s0>>>(Wp, bp, x_cls, out_cls);
    k_opatch<<<dim3(4, BATCH, 2), 256, 0, s0>>>(patch, out_cls);
    k_im2colT<<<(BATCH*NP*KPAD)/256, 256, 0, s0>>>();
    cudaStreamWaitEvent(s0, e3, 0);
    gemm_mma<1><<<dim3(8, 6, BATCH), 256, SMEMB, s0>>>(nullptr, y);
}

// round 13
// speedup vs baseline: 1.0572x; 1.0086x over previous
#include <cuda_runtime.h>
#include <cuda_fp16.h>
#include <cstdint>
#include <math.h>

#define EPSV 1e-5f
#define BATCH 16
#define CLSN 20
#define CDIM 768
#define NHEADS 4
#define DHEAD 192
#define NP 1024
#define ROWS (BATCH*CLSN)
#define PPB (CDIM*NP)
#define KPAD 192

// ---------------- scratch ----------------------------------------------------
__device__ float g_xln[ROWS*CDIM];
__device__ float g_q[ROWS*CDIM];
__device__ float g_sums[32];
__device__ float g_rowsum[BATCH*NHEADS*CLSN];
__device__ float g_outflat[ROWS*CDIM];
__device__ float g_opatch[BATCH*CLSN*NP];
__device__ float g_alpha[CDIM];
__device__ float g_beta[CDIM];
__device__ __align__(128) __half g_kvh[BATCH*2*CDIM*NP];  // 50 MB fp16
__device__ __align__(128) __half g_Wkvh[2*CDIM*CDIM];
__device__ __align__(128) __half g_nxTh[BATCH*NP*CDIM];   // [b][n][c]
__device__ __align__(128) __half g_W2h[CDIM*KPAD];
__device__ __align__(128) __half g_ich[BATCH*NP*KPAD];    // [b][n][k]

__device__ __forceinline__ float gelu_exact(float x) {
    return 0.5f * x * (1.0f + erff(x * 0.70710678118654752440f));
}
__device__ __forceinline__ uint32_t s2u(const void* p) {
    uint32_t a;
    asm("{ .reg .u64 t; cvta.to.shared.u64 t, %1; cvt.u32.u64 %0, t; }" : "=r"(a) : "l"(p));
    return a;
}
__device__ __forceinline__ void cp16(uint32_t dst, const void* src) {
    asm volatile("cp.async.cg.shared.global [%0], [%1], 16;" :: "r"(dst), "l"(src));
}
#define CP_COMMIT() asm volatile("cp.async.commit_group;" ::: "memory")
#define LDSM_X4(r0,r1,r2,r3,a) \
    asm volatile("ldmatrix.sync.aligned.m8n8.x4.shared.b16 {%0,%1,%2,%3}, [%4];" \
                 : "=r"(r0), "=r"(r1), "=r"(r2), "=r"(r3) : "r"(a))
#define MMA16816(c, a, b0, b1) \
    asm volatile("mma.sync.aligned.m16n8k16.row.col.f32.f16.f16.f32 " \
                 "{%0,%1,%2,%3}, {%4,%5,%6,%7}, {%8,%9}, {%0,%1,%2,%3};" \
                 : "+f"((c)[0]), "+f"((c)[1]), "+f"((c)[2]), "+f"((c)[3]) \
                 : "r"((a)[0]), "r"((a)[1]), "r"((a)[2]), "r"((a)[3]), "r"(b0), "r"(b1))

// ---------------- zero all atomic targets ------------------------------------
__global__ void k_zero(float* __restrict__ out_cls) {
    int i = blockIdx.x * 256 + threadIdx.x;
    if (i < ROWS*CDIM) { g_outflat[i] = 0.0f; g_q[i] = 0.0f; out_cls[i] = 0.0f; }
    if (i < BATCH*CLSN*NP) g_opatch[i] = 0.0f;
    if (i < BATCH*NHEADS*CLSN) g_rowsum[i] = 0.0f;
    if (i < 32) g_sums[i] = 0.0f;
}

__global__ void k_lncls(const float* __restrict__ x, const float* __restrict__ w,
                        const float* __restrict__ bb) {
    int r = blockIdx.x, tid = threadIdx.x;
    const float* xr = x + r * CDIM;
    float v0 = xr[tid], v1 = xr[tid+256], v2 = xr[tid+512];
    __shared__ float red[256];
    __shared__ float s_mu, s_rs;
    red[tid] = v0 + v1 + v2; __syncthreads();
    for (int o = 128; o; o >>= 1) { if (tid < o) red[tid] += red[tid+o]; __syncthreads(); }
    if (tid == 0) s_mu = red[0] * (1.0f/768.0f);
    __syncthreads();
    float mu = s_mu;
    float d0 = v0-mu, d1 = v1-mu, d2 = v2-mu;
    red[tid] = d0*d0 + d1*d1 + d2*d2; __syncthreads();
    for (int o = 128; o; o >>= 1) { if (tid < o) red[tid] += red[tid+o]; __syncthreads(); }
    if (tid == 0) s_rs = rsqrtf(red[0] * (1.0f/768.0f) + EPSV);
    __syncthreads();
    float rs = s_rs;
    float* o = g_xln + r * CDIM;
    o[tid]     = d0*rs*w[tid]     + bb[tid];
    o[tid+256] = d1*rs*w[tid+256] + bb[tid+256];
    o[tid+512] = d2*rs*w[tid+512] + bb[tid+512];
}

__global__ void k_psum(const float* __restrict__ x) {
    int b = blockIdx.y, tid = threadIdx.x;
    const float* p = x + (size_t)b * PPB + blockIdx.x * 16384 + tid;
    float s = 0.0f, q = 0.0f;
    #pragma unroll 8
    for (int i = 0; i < 64; i++) { float v = p[i*256]; s += v; q += v*v; }
    __shared__ float rs[256], rq[256];
    rs[tid] = s; rq[tid] = q; __syncthreads();
    for (int o = 128; o; o >>= 1) {
        if (tid < o) { rs[tid] += rs[tid+o]; rq[tid] += rq[tid+o]; }
        __syncthreads();
    }
    if (tid == 0) { atomicAdd(&g_sums[b], rs[0]); atomicAdd(&g_sums[16+b], rq[0]); }
}

// normalize + transpose + fp16:  g_nxTh[b][n][c]
__global__ void __launch_bounds__(256) k_nxT(const float* __restrict__ x,
                                             const float* __restrict__ w,
                                             const float* __restrict__ bb) {
    __shared__ float t[32][33];
    int b = blockIdx.z, c0 = blockIdx.y*32, n0 = blockIdx.x*32;
    int tx = threadIdx.x & 31, ty = threadIdx.x >> 5;
    float mu  = g_sums[b]    * (1.0f/786432.0f);
    float var = g_sums[16+b] * (1.0f/786432.0f) - mu*mu;
    float rv = rsqrtf(var + EPSV);
    #pragma unroll
    for (int i = 0; i < 4; i++) {
        int c = c0 + ty + i*8;
        float v = x[(size_t)b*PPB + (size_t)c*NP + n0 + tx];
        t[tx][ty + i*8] = (v - mu)*rv*w[c] + bb[c];
    }
    __syncthreads();
    #pragma unroll
    for (int i = 0; i < 4; i++) {
        int n = n0 + ty + i*8;
        float v = t[ty + i*8][tx];
        g_nxTh[((size_t)b*NP + n)*CDIM + c0 + tx] = __float2half_rn(v);
    }
}

__global__ void k_prep_wkv(const float* __restrict__ W) {
    int i = blockIdx.x * 256 + threadIdx.x;
    if (i < 2*CDIM*CDIM) g_Wkvh[i] = __float2half_rn(W[i]);
}

__global__ void k_prepconv(const float* __restrict__ Wc, const float* __restrict__ bc,
                           const float* __restrict__ g,  const float* __restrict__ bt,
                           const float* __restrict__ mn, const float* __restrict__ vr) {
    int i = blockIdx.x * 256 + threadIdx.x;
    if (i < CDIM*KPAD) {
        int o = i / KPAD, k = i - o*KPAD;
        g_W2h[i] = __float2half_rn((k < 180) ? Wc[o*180 + k] : 0.0f);
    }
    if (i < CDIM) {
        float al = g[i] * rsqrtf(vr[i] + EPSV);
        g_alpha[i] = al;
        g_beta[i]  = (bc[i] - mn[i]) * al + bt[i];
    }
}

// ---------------- small NT GEMM, split-K x2 (q proj / out proj) --------------
template<int MODE>
__global__ void __launch_bounds__(256) gemm_nt(const float* __restrict__ Bw,
                                               const float* __restrict__ bias,
                                               const float* __restrict__ res,
                                               float* __restrict__ Cext) {
    const float* A = (MODE == 0) ? g_xln : g_outflat;
    float* C = (MODE == 0) ? g_q : Cext;
    __shared__ float As[16*68];
    __shared__ float Bs[16*68];
    int m0 = blockIdx.y * 64, n0 = blockIdx.x * 64, kz = blockIdx.z;
    int tid = threadIdx.x, tx = tid & 15, ty = tid >> 4;
    float acc[4][4] = {};
    int row = tid >> 2, kq = tid & 3;
    for (int k0 = kz*384; k0 < kz*384 + 384; k0 += 16) {
        float4 va = *(const float4*)(A  + (m0+row)*768 + k0 + kq*4);
        float4 vb = *(const float4*)(Bw + (n0+row)*768 + k0 + kq*4);
        As[(kq*4+0)*68+row] = va.x; As[(kq*4+1)*68+row] = va.y;
        As[(kq*4+2)*68+row] = va.z; As[(kq*4+3)*68+row] = va.w;
        Bs[(kq*4+0)*68+row] = vb.x; Bs[(kq*4+1)*68+row] = vb.y;
        Bs[(kq*4+2)*68+row] = vb.z; Bs[(kq*4+3)*68+row] = vb.w;
        __syncthreads();
        #pragma unroll
        for (int k = 0; k < 16; k++) {
            float4 a4 = *(const float4*)(&As[k*68 + ty*4]);
            float4 b4 = *(const float4*)(&Bs[k*68 + tx*4]);
            float am[4] = {a4.x, a4.y, a4.z, a4.w};
            float bn[4] = {b4.x, b4.y, b4.z, b4.w};
            #pragma unroll
            for (int i = 0; i < 4; i++)
                #pragma unroll
                for (int j = 0; j < 4; j++) acc[i][j] += am[i]*bn[j];
        }
        __syncthreads();
    }
    #pragma unroll
    for (int i = 0; i < 4; i++) {
        int m = m0 + ty*4 + i;
        #pragma unroll
        for (int j = 0; j < 4; j++) {
            int n = n0 + tx*4 + j;
            float add = 0.0f;
            if (kz == 0) {
                add = bias[n];
                if (MODE == 1) add += res[m*768 + n];
            }
            atomicAdd(&C[m*768 + n], acc[i][j] + add);
        }
    }
}

// ---------------- mma.sync fp16 GEMM, k32 slabs ------------------------------
#define TPITCH 80
#define TBYTES (128*TPITCH)
#define STAGEB (2*TBYTES)
#define NSTG 3
#define SMEMB (NSTG*STAGEB)          /* 61440 */
template<int MODE>
__global__ void __launch_bounds__(256, 2) gemm_mma(const float* __restrict__ bias,
                                                   float* __restrict__ Cout) {
    const int K  = (MODE == 0) ? 768 : KPAD;
    const int NS = K / 32;
    extern __shared__ __align__(1024) char sm[];
    uint32_t sb = s2u(sm);
    int tid = threadIdx.x;
    int w = tid >> 5, l = tid & 31;
    int wm = w >> 1, wn = w & 1;
    int b = blockIdx.z;
    int m0 = blockIdx.y * 128, n0 = blockIdx.x * 128;

    const __half* Ah = (MODE == 0) ? g_Wkvh : g_W2h;
    const __half* Bh = ((MODE == 0) ? g_nxTh : g_ich) + (size_t)b * NP * K;
    __half* Ch = g_kvh + (size_t)b * 2*CDIM*NP;
    float* Cf  = Cout + (size_t)b * CDIM*NP;

    float acc[2][8][4] = {};

    int r0 = tid >> 2, q0 = tid & 3;
    int r1 = ((tid + 256) >> 2), q1 = q0;

    auto load_stage = [&](int s) {
        uint32_t st = sb + (s % NSTG) * STAGEB;
        int k0 = s * 32;
        cp16(st + r0*TPITCH + q0*16,          Ah + (size_t)(m0+r0)*K + k0 + q0*8);
        cp16(st + r1*TPITCH + q1*16,          Ah + (size_t)(m0+r1)*K + k0 + q1*8);
        cp16(st + TBYTES + r0*TPITCH + q0*16, Bh + (size_t)(n0+r0)*K + k0 + q0*8);
        cp16(st + TBYTES + r1*TPITCH + q1*16, Bh + (size_t)(n0+r1)*K + k0 + q1*8);
        CP_COMMIT();
    };
    load_stage(0);
    load_stage(1);

    int lrow = (l & 7) + ((l >> 3) & 1) * 8;
    int lko  = (l >> 4) * 16;

    for (int s = 0; s < NS; s++) {
        if (s + 1 < NS) asm volatile("cp.async.wait_group 1;" ::: "memory");
        else            asm volatile("cp.async.wait_group 0;" ::: "memory");
        __syncthreads();
        if (s + 2 < NS) load_stage(s + 2);
        uint32_t st = sb + (s % NSTG) * STAGEB;
        #pragma unroll
        for (int kk = 0; kk < 2; kk++) {
            uint32_t aro = st + (wm*32 + lrow)*TPITCH + lko + kk*32;
            uint32_t bro = st + TBYTES + (wn*64 + lrow)*TPITCH + lko + kk*32;
            uint32_t ah[2][4], bf[4][4];
            #pragma unroll
            for (int mi = 0; mi < 2; mi++)
                LDSM_X4(ah[mi][0], ah[mi][1], ah[mi][2], ah[mi][3], aro + mi*16*TPITCH);
            #pragma unroll
            for (int np = 0; np < 4; np++)
                LDSM_X4(bf[np][0], bf[np][1], bf[np][2], bf[np][3], bro + np*16*TPITCH);
            #pragma unroll
            for (int mi = 0; mi < 2; mi++)
                #pragma unroll
                for (int ni = 0; ni < 8; ni++) {
                    int np = ni >> 1;
                    uint32_t b0r = (ni & 1) ? bf[np][1] : bf[np][0];
                    uint32_t b1r = (ni & 1) ? bf[np][3] : bf[np][2];
                    MMA16816(acc[mi][ni], ah[mi], b0r, b1r);
                }
        }
    }

    // epilogue
    #pragma unroll
    for (int mi = 0; mi < 2; mi++) {
        int rA = m0 + wm*32 + mi*16 + (l >> 2);
        int rB = rA + 8;
        float pA0, pA1, pB0, pB1;
        if (MODE == 0) { pA0 = bias[rA]; pA1 = 0.0f; pB0 = bias[rB]; pB1 = 0.0f; }
        else { pA0 = g_alpha[rA]; pA1 = g_beta[rA]; pB0 = g_alpha[rB]; pB1 = g_beta[rB]; }
        #pragma unroll
        for (int ni = 0; ni < 8; ni++) {
            int col = n0 + wn*64 + ni*8 + (l & 3)*2;
            float* c = acc[mi][ni];
            if (MODE == 0) {
                *(__half2*)(Ch + (size_t)rA*NP + col) = __floats2half2_rn(c[0]+pA0, c[1]+pA0);
                *(__half2*)(Ch + (size_t)rB*NP + col) = __floats2half2_rn(c[2]+pB0, c[3]+pB0);
            } else {
                *(float2*)(Cf + (size_t)rA*NP + col) =
                    make_float2(gelu_exact(c[0]*pA0 + pA1), gelu_exact(c[1]*pA0 + pA1));
                *(float2*)(Cf + (size_t)rB*NP + col) =
                    make_float2(gelu_exact(c[2]*pB0 + pB1), gelu_exact(c[3]*pB0 + pB1));
            }
        }
    }
}

// ---------------- fused attention: logits+exp in smem, AV, rowsum ------------
// grid (4, NHEADS, BATCH), 256 threads. outflat accumulates UNNORMALIZED;
// k_norm divides by rowsum afterwards.
__global__ void __launch_bounds__(256) k_attn() {
    int chunk = blockIdx.x, h = blockIdx.y, b = blockIdx.z;
    int tid = threadIdx.x, l = tid & 31;
    __shared__ float qs[CLSN*DHEAD];
    __shared__ float ps[CLSN*256];
    __shared__ float bsum[CLSN];
    const float scale = 0.07216878364870322f;   // 1/sqrt(192)
    for (int i = tid; i < CLSN*DHEAD; i += 256) {
        int m = i / DHEAD, d = i - m*DHEAD;
        qs[i] = g_q[(b*CLSN + m)*CDIM + h*DHEAD + d] * scale;
    }
    if (tid < CLSN) bsum[tid] = 0.0f;
    __syncthreads();
    // logits + exp for n = chunk*256 + tid
    {
        int n = chunk*256 + tid;
        const __half* kvp = g_kvh + ((size_t)b*2*CDIM + h*DHEAD)*NP + n;
        float acc[CLSN] = {};
        for (int d = 0; d < DHEAD; d++) {
            float kval = __half2float(kvp[(size_t)d * NP]);
            #pragma unroll
            for (int m = 0; m < CLSN; m++) acc[m] += qs[m*DHEAD + d] * kval;
        }
        #pragma unroll
        for (int m = 0; m < CLSN; m++) {
            float e = __expf(acc[m]);
            ps[m*256 + tid] = e;
            #pragma unroll
            for (int o = 16; o; o >>= 1) e += __shfl_xor_sync(0xFFFFFFFFu, e, o);
            if (l == 0) atomicAdd(&bsum[m], e);
        }
    }
    __syncthreads();
    if (tid < CLSN)
        atomicAdd(&g_rowsum[((size_t)(b*NHEADS + h))*CLSN + tid], bsum[tid]);
    // AV: threads 0..191 own d
    if (tid < DHEAD) {
        const __half* vp = g_kvh + ((size_t)b*2*CDIM + CDIM + h*DHEAD + tid)*NP + chunk*256;
        float acc[CLSN] = {};
        for (int nn = 0; nn < 256; nn += 2) {
            float2 vv = __half22float2(*(const __half2*)(vp + nn));
            #pragma unroll
            for (int m = 0; m < CLSN; m++)
                acc[m] += ps[m*256 + nn]*vv.x + ps[m*256 + nn + 1]*vv.y;
        }
        #pragma unroll
        for (int m = 0; m < CLSN; m++)
            atomicAdd(&g_outflat[(b*CLSN + m)*CDIM + h*DHEAD + tid], acc[m]);
    }
}

// ---------------- normalize outflat by rowsum --------------------------------
__global__ void k_norm() {
    int i = blockIdx.x * 256 + threadIdx.x;
    if (i < ROWS*CDIM) {
        int r = i / CDIM, c = i - r*CDIM;
        int b = r / CLSN, m = r - b*CLSN, h = c / DHEAD;
        g_outflat[i] *= 1.0f / g_rowsum[((size_t)(b*NHEADS + h))*CLSN + m];
    }
}

// ---------------- out_patch = out_cls @ input_patch, split-K x2 --------------
__global__ void __launch_bounds__(256) k_opatch(const float* __restrict__ patch,
                                                const float* __restrict__ ocls) {
    int chunk = blockIdx.x, b = blockIdx.y, kz = blockIdx.z;
    int tid = threadIdx.x;
    int n = chunk*256 + tid;
    __shared__ float a_s[CLSN*96];
    float acc[CLSN] = {};
    for (int k0 = kz*384; k0 < kz*384 + 384; k0 += 96) {
        __syncthreads();
        for (int i = tid; i < CLSN*96; i += 256) {
            int m = i / 96, kk = i - m*96;
            a_s[i] = ocls[(b*CLSN + m)*CDIM + k0 + kk];
        }
        __syncthreads();
        for (int kk = 0; kk < 96; kk++) {
            float pv = patch[(size_t)b*PPB + (size_t)(k0+kk)*NP + n];
            #pragma unroll
            for (int m = 0; m < CLSN; m++) acc[m] += a_s[m*96 + kk] * pv;
        }
    }
    #pragma unroll
    for (int m = 0; m < CLSN; m++)
        atomicAdd(&g_opatch[((size_t)b*CLSN + m)*NP + n], acc[m]);
}

// ---------------- im2col transposed + fp16 -----------------------------------
__global__ void k_im2colT() {
    int i = blockIdx.x * 256 + threadIdx.x;
    int b = i / (NP*KPAD);
    int rest = i - b * NP*KPAD;
    int n = rest / KPAD, k = rest - n*KPAD;
    float val = 0.0f;
    if (k < 180) {
        int ic = k / 9, t = k - ic*9;
        int hh = (n >> 5) + t/3 - 1, ww = (n & 31) + t%3 - 1;
        if (hh >= 0 && hh < 32 && ww >= 0 && ww < 32)
            val = g_opatch[((size_t)b*CLSN + ic)*NP + hh*32 + ww];
    }
    g_ich[i] = __float2half_rn(val);
}

// ---------------- launcher ---------------------------------------------------
extern "C" void kernel_launch(void* const* d_in, const int* in_sizes, int n_in,
                              void* d_out, int out_size) {
    const float* x_cls  = (const float*)d_in[0];
    const float* patch  = (const float*)d_in[1];
    const float* ln_w   = (const float*)d_in[2];
    const float* ln_b   = (const float*)d_in[3];
    const float* nx_w   = (const float*)d_in[4];
    const float* nx_b   = (const float*)d_in[5];
    const float* Wq     = (const float*)d_in[6];
    const float* bq     = (const float*)d_in[7];
    const float* Wkv    = (const float*)d_in[8];
    const float* bkv    = (const float*)d_in[9];
    const float* Wp     = (const float*)d_in[10];
    const float* bp     = (const float*)d_in[11];
    const float* Wconv  = (const float*)d_in[12];
    const float* bconv  = (const float*)d_in[13];
    const float* bn_g   = (const float*)d_in[14];
    const float* bn_b   = (const float*)d_in[15];
    const float* bn_m   = (const float*)d_in[16];
    const float* bn_v   = (const float*)d_in[17];
    float* out_cls = (float*)d_out;
    float* y       = out_cls + ROWS*CDIM;

    static cudaStream_t s1 = nullptr, s2 = nullptr;
    static cudaEvent_t e0, e1, e2, e3;
    if (!s1) {
        cudaStreamCreateWithFlags(&s1, cudaStreamNonBlocking);
        cudaStreamCreateWithFlags(&s2, cudaStreamNonBlocking);
        cudaEventCreateWithFlags(&e0, cudaEventDisableTiming);
        cudaEventCreateWithFlags(&e1, cudaEventDisableTiming);
        cudaEventCreateWithFlags(&e2, cudaEventDisableTiming);
        cudaEventCreateWithFlags(&e3, cudaEventDisableTiming);
        cudaFuncSetAttribute(gemm_mma<0>, cudaFuncAttributeMaxDynamicSharedMemorySize, SMEMB);
        cudaFuncSetAttribute(gemm_mma<1>, cudaFuncAttributeMaxDynamicSharedMemorySize, SMEMB);
    }
    cudaStream_t s0 = 0;

    // ---- fork point: everything depends on k_zero ----
    k_zero<<<1280, 256, 0, s0>>>(out_cls);
    cudaEventRecord(e0, s0);

    // side chain 1: cls LN + q projection (joined before k_attn)
    cudaStreamWaitEvent(s1, e0, 0);
    k_lncls<<<ROWS, 256, 0, s1>>>(x_cls, ln_w, ln_b);
    gemm_nt<0><<<dim3(12, 5, 2), 256, 0, s1>>>(Wq, bq, nullptr, nullptr);
    cudaEventRecord(e1, s1);

    // side chain 2: weight preps (joined before their consumer GEMMs)
    cudaStreamWaitEvent(s2, e0, 0);
    k_prep_wkv<<<(2*CDIM*CDIM)/256, 256, 0, s2>>>(Wkv);
    cudaEventRecord(e2, s2);
    k_prepconv<<<(CDIM*KPAD + 255)/256, 256, 0, s2>>>(Wconv, bconv, bn_g, bn_b, bn_m, bn_v);
    cudaEventRecord(e3, s2);

    // main chain (critical path)
    k_psum<<<dim3(48, BATCH), 256, 0, s0>>>(patch);
    k_nxT<<<dim3(32, 24, BATCH), 256, 0, s0>>>(patch, nx_w, nx_b);
    cudaStreamWaitEvent(s0, e2, 0);
    gemm_mma<0><<<dim3(8, 12, BATCH), 256, SMEMB, s0>>>(bkv, nullptr);
    cudaStreamWaitEvent(s0, e1, 0);
    k_attn<<<dim3(4, NHEADS, BATCH), 256, 0, s0>>>();
    k_norm<<<(ROWS*CDIM + 255)/256, 256, 0, s0>>>();
    gemm_nt<1><<<dim3(12, 5, 2), 256, 0, s0>>>(Wp, bp, x_cls, out_cls);
    k_opatch<<<dim3(4, BATCH, 2), 256, 0, s0>>>(patch, out_cls);
    k_im2colT<<<(BATCH*NP*KPAD)/256, 256, 0, s0>>>();
    cudaStreamWaitEvent(s0, e3, 0);
    gemm_mma<1><<<dim3(8, 6, BATCH), 256, SMEMB, s0>>>(nullptr, y);
}

// round 14
// speedup vs baseline: 1.0615x; 1.0041x over previous
#include <cuda_runtime.h>
#include <cuda_fp16.h>
#include <cstdint>
#include <math.h>

#define EPSV 1e-5f
#define BATCH 16
#define CLSN 20
#define CDIM 768
#define NHEADS 4
#define DHEAD 192
#define NP 1024
#define ROWS (BATCH*CLSN)
#define PPB (CDIM*NP)
#define KPAD 192

// ---------------- scratch ----------------------------------------------------
__device__ float g_xln[ROWS*CDIM];
__device__ float g_q[ROWS*CDIM];
__device__ float g_sums[32];
__device__ float g_rowsum[BATCH*NHEADS*CLSN];
__device__ float g_outflat[ROWS*CDIM];
__device__ float g_opatch[BATCH*CLSN*NP];
__device__ float g_alpha[CDIM];
__device__ float g_beta[CDIM];
__device__ __align__(128) __half g_kvh[BATCH*2*CDIM*NP];  // 50 MB fp16
__device__ __align__(128) __half g_Wkvh[2*CDIM*CDIM];
__device__ __align__(128) __half g_nxTh[BATCH*NP*CDIM];   // [b][n][c]
__device__ __align__(128) __half g_W2h[CDIM*KPAD];
__device__ __align__(128) __half g_ich[BATCH*NP*KPAD];    // [b][n][k]

__device__ __forceinline__ float gelu_exact(float x) {
    return 0.5f * x * (1.0f + erff(x * 0.70710678118654752440f));
}
__device__ __forceinline__ uint32_t s2u(const void* p) {
    uint32_t a;
    asm("{ .reg .u64 t; cvta.to.shared.u64 t, %1; cvt.u32.u64 %0, t; }" : "=r"(a) : "l"(p));
    return a;
}
__device__ __forceinline__ void cp16(uint32_t dst, const void* src) {
    asm volatile("cp.async.cg.shared.global [%0], [%1], 16;" :: "r"(dst), "l"(src));
}
#define CP_COMMIT() asm volatile("cp.async.commit_group;" ::: "memory")
#define LDSM_X4(r0,r1,r2,r3,a) \
    asm volatile("ldmatrix.sync.aligned.m8n8.x4.shared.b16 {%0,%1,%2,%3}, [%4];" \
                 : "=r"(r0), "=r"(r1), "=r"(r2), "=r"(r3) : "r"(a))
#define MMA16816(c, a, b0, b1) \
    asm volatile("mma.sync.aligned.m16n8k16.row.col.f32.f16.f16.f32 " \
                 "{%0,%1,%2,%3}, {%4,%5,%6,%7}, {%8,%9}, {%0,%1,%2,%3};" \
                 : "+f"((c)[0]), "+f"((c)[1]), "+f"((c)[2]), "+f"((c)[3]) \
                 : "r"((a)[0]), "r"((a)[1]), "r"((a)[2]), "r"((a)[3]), "r"(b0), "r"(b1))

// ---------------- zeroing: small (critical path) + big (side stream) ---------
__global__ void k_zero_small() {
    int i = threadIdx.x + blockIdx.x * 256;
    if (i < 32) g_sums[i] = 0.0f;
    if (i < BATCH*NHEADS*CLSN) g_rowsum[i] = 0.0f;
}
__global__ void k_zero_big(float* __restrict__ out_cls) {
    int i = blockIdx.x * 256 + threadIdx.x;
    if (i < ROWS*CDIM) { g_outflat[i] = 0.0f; out_cls[i] = 0.0f; }
    if (i < BATCH*CLSN*NP) g_opatch[i] = 0.0f;
}

__global__ void k_lncls(const float* __restrict__ x, const float* __restrict__ w,
                        const float* __restrict__ bb) {
    int r = blockIdx.x, tid = threadIdx.x;
    const float* xr = x + r * CDIM;
    float v0 = xr[tid], v1 = xr[tid+256], v2 = xr[tid+512];
    __shared__ float red[256];
    __shared__ float s_mu, s_rs;
    red[tid] = v0 + v1 + v2; __syncthreads();
    for (int o = 128; o; o >>= 1) { if (tid < o) red[tid] += red[tid+o]; __syncthreads(); }
    if (tid == 0) s_mu = red[0] * (1.0f/768.0f);
    __syncthreads();
    float mu = s_mu;
    float d0 = v0-mu, d1 = v1-mu, d2 = v2-mu;
    red[tid] = d0*d0 + d1*d1 + d2*d2; __syncthreads();
    for (int o = 128; o; o >>= 1) { if (tid < o) red[tid] += red[tid+o]; __syncthreads(); }
    if (tid == 0) s_rs = rsqrtf(red[0] * (1.0f/768.0f) + EPSV);
    __syncthreads();
    float rs = s_rs;
    float* o = g_xln + r * CDIM;
    o[tid]     = d0*rs*w[tid]     + bb[tid];
    o[tid+256] = d1*rs*w[tid+256] + bb[tid+256];
    o[tid+512] = d2*rs*w[tid+512] + bb[tid+512];
}

__global__ void k_psum(const float* __restrict__ x) {
    int b = blockIdx.y, tid = threadIdx.x;
    const float* p = x + (size_t)b * PPB + blockIdx.x * 16384 + tid;
    float s = 0.0f, q = 0.0f;
    #pragma unroll 8
    for (int i = 0; i < 64; i++) { float v = p[i*256]; s += v; q += v*v; }
    __shared__ float rs[256], rq[256];
    rs[tid] = s; rq[tid] = q; __syncthreads();
    for (int o = 128; o; o >>= 1) {
        if (tid < o) { rs[tid] += rs[tid+o]; rq[tid] += rq[tid+o]; }
        __syncthreads();
    }
    if (tid == 0) { atomicAdd(&g_sums[b], rs[0]); atomicAdd(&g_sums[16+b], rq[0]); }
}

// normalize + transpose + fp16:  g_nxTh[b][n][c]
__global__ void __launch_bounds__(256) k_nxT(const float* __restrict__ x,
                                             const float* __restrict__ w,
                                             const float* __restrict__ bb) {
    __shared__ float t[32][33];
    int b = blockIdx.z, c0 = blockIdx.y*32, n0 = blockIdx.x*32;
    int tx = threadIdx.x & 31, ty = threadIdx.x >> 5;
    float mu  = g_sums[b]    * (1.0f/786432.0f);
    float var = g_sums[16+b] * (1.0f/786432.0f) - mu*mu;
    float rv = rsqrtf(var + EPSV);
    #pragma unroll
    for (int i = 0; i < 4; i++) {
        int c = c0 + ty + i*8;
        float v = x[(size_t)b*PPB + (size_t)c*NP + n0 + tx];
        t[tx][ty + i*8] = (v - mu)*rv*w[c] + bb[c];
    }
    __syncthreads();
    #pragma unroll
    for (int i = 0; i < 4; i++) {
        int n = n0 + ty + i*8;
        float v = t[ty + i*8][tx];
        g_nxTh[((size_t)b*NP + n)*CDIM + c0 + tx] = __float2half_rn(v);
    }
}

__global__ void k_prep_wkv(const float* __restrict__ W) {
    int i = blockIdx.x * 256 + threadIdx.x;
    if (i < 2*CDIM*CDIM) g_Wkvh[i] = __float2half_rn(W[i]);
}

__global__ void k_prepconv(const float* __restrict__ Wc, const float* __restrict__ bc,
                           const float* __restrict__ g,  const float* __restrict__ bt,
                           const float* __restrict__ mn, const float* __restrict__ vr) {
    int i = blockIdx.x * 256 + threadIdx.x;
    if (i < CDIM*KPAD) {
        int o = i / KPAD, k = i - o*KPAD;
        g_W2h[i] = __float2half_rn((k < 180) ? Wc[o*180 + k] : 0.0f);
    }
    if (i < CDIM) {
        float al = g[i] * rsqrtf(vr[i] + EPSV);
        g_alpha[i] = al;
        g_beta[i]  = (bc[i] - mn[i]) * al + bt[i];
    }
}

// ---------------- small NT GEMM --------------------------------------------
// MODE 0: q proj, single pass, direct write (side stream, latency hidden).
// MODE 1: out proj, split-K x2 via blockIdx.z, atomics; A scaled by 1/rowsum.
template<int MODE>
__global__ void __launch_bounds__(256) gemm_nt(const float* __restrict__ Bw,
                                               const float* __restrict__ bias,
                                               const float* __restrict__ res,
                                               float* __restrict__ Cext) {
    const float* A = (MODE == 0) ? g_xln : g_outflat;
    float* C = (MODE == 0) ? g_q : Cext;
    __shared__ float As[16*68];
    __shared__ float Bs[16*68];
    int m0 = blockIdx.y * 64, n0 = blockIdx.x * 64, kz = (MODE == 0) ? 0 : blockIdx.z;
    const int KB = (MODE == 0) ? 768 : 384;
    int tid = threadIdx.x, tx = tid & 15, ty = tid >> 4;
    float acc[4][4] = {};
    int row = tid >> 2, kq = tid & 3;
    int m = m0 + row;
    int bb_ = m / CLSN, mc = m - bb_*CLSN;        // MODE 1 rowsum index parts
    for (int k0 = kz*384; k0 < kz*384 + KB; k0 += 16) {
        float4 va = *(const float4*)(A  + (size_t)m*768 + k0 + kq*4);
        float4 vb = *(const float4*)(Bw + (size_t)(n0+row)*768 + k0 + kq*4);
        if (MODE == 1) {
            int h = (k0 + kq*4) / DHEAD;
            float inv = 1.0f / g_rowsum[((size_t)(bb_*NHEADS + h))*CLSN + mc];
            va.x *= inv; va.y *= inv; va.z *= inv; va.w *= inv;
        }
        As[(kq*4+0)*68+row] = va.x; As[(kq*4+1)*68+row] = va.y;
        As[(kq*4+2)*68+row] = va.z; As[(kq*4+3)*68+row] = va.w;
        Bs[(kq*4+0)*68+row] = vb.x; Bs[(kq*4+1)*68+row] = vb.y;
        Bs[(kq*4+2)*68+row] = vb.z; Bs[(kq*4+3)*68+row] = vb.w;
        __syncthreads();
        #pragma unroll
        for (int k = 0; k < 16; k++) {
            float4 a4 = *(const float4*)(&As[k*68 + ty*4]);
            float4 b4 = *(const float4*)(&Bs[k*68 + tx*4]);
            float am[4] = {a4.x, a4.y, a4.z, a4.w};
            float bn[4] = {b4.x, b4.y, b4.z, b4.w};
            #pragma unroll
            for (int i = 0; i < 4; i++)
                #pragma unroll
                for (int j = 0; j < 4; j++) acc[i][j] += am[i]*bn[j];
        }
        __syncthreads();
    }
    #pragma unroll
    for (int i = 0; i < 4; i++) {
        int mm = m0 + ty*4 + i;
        #pragma unroll
        for (int j = 0; j < 4; j++) {
            int n = n0 + tx*4 + j;
            if (MODE == 0) {
                C[mm*768 + n] = acc[i][j] + bias[n];
            } else {
                float add = 0.0f;
                if (kz == 0) add = bias[n] + res[mm*768 + n];
                atomicAdd(&C[mm*768 + n], acc[i][j] + add);
            }
        }
    }
}

// ---------------- mma.sync fp16 GEMM, k32 slabs ------------------------------
#define TPITCH 80
#define TBYTES (128*TPITCH)
#define STAGEB (2*TBYTES)
#define NSTG 3
#define SMEMB (NSTG*STAGEB)          /* 61440 */
template<int MODE>
__global__ void __launch_bounds__(256, 2) gemm_mma(const float* __restrict__ bias,
                                                   float* __restrict__ Cout) {
    const int K  = (MODE == 0) ? 768 : KPAD;
    const int NS = K / 32;
    extern __shared__ __align__(1024) char sm[];
    uint32_t sb = s2u(sm);
    int tid = threadIdx.x;
    int w = tid >> 5, l = tid & 31;
    int wm = w >> 1, wn = w & 1;
    int b = blockIdx.z;
    int m0 = blockIdx.y * 128, n0 = blockIdx.x * 128;

    const __half* Ah = (MODE == 0) ? g_Wkvh : g_W2h;
    const __half* Bh = ((MODE == 0) ? g_nxTh : g_ich) + (size_t)b * NP * K;
    __half* Ch = g_kvh + (size_t)b * 2*CDIM*NP;
    float* Cf  = Cout + (size_t)b * CDIM*NP;

    float acc[2][8][4] = {};

    int r0 = tid >> 2, q0 = tid & 3;
    int r1 = ((tid + 256) >> 2), q1 = q0;

    auto load_stage = [&](int s) {
        uint32_t st = sb + (s % NSTG) * STAGEB;
        int k0 = s * 32;
        cp16(st + r0*TPITCH + q0*16,          Ah + (size_t)(m0+r0)*K + k0 + q0*8);
        cp16(st + r1*TPITCH + q1*16,          Ah + (size_t)(m0+r1)*K + k0 + q1*8);
        cp16(st + TBYTES + r0*TPITCH + q0*16, Bh + (size_t)(n0+r0)*K + k0 + q0*8);
        cp16(st + TBYTES + r1*TPITCH + q1*16, Bh + (size_t)(n0+r1)*K + k0 + q1*8);
        CP_COMMIT();
    };
    load_stage(0);
    load_stage(1);

    int lrow = (l & 7) + ((l >> 3) & 1) * 8;
    int lko  = (l >> 4) * 16;

    for (int s = 0; s < NS; s++) {
        if (s + 1 < NS) asm volatile("cp.async.wait_group 1;" ::: "memory");
        else            asm volatile("cp.async.wait_group 0;" ::: "memory");
        __syncthreads();
        if (s + 2 < NS) load_stage(s + 2);
        uint32_t st = sb + (s % NSTG) * STAGEB;
        #pragma unroll
        for (int kk = 0; kk < 2; kk++) {
            uint32_t aro = st + (wm*32 + lrow)*TPITCH + lko + kk*32;
            uint32_t bro = st + TBYTES + (wn*64 + lrow)*TPITCH + lko + kk*32;
            uint32_t ah[2][4], bf[4][4];
            #pragma unroll
            for (int mi = 0; mi < 2; mi++)
                LDSM_X4(ah[mi][0], ah[mi][1], ah[mi][2], ah[mi][3], aro + mi*16*TPITCH);
            #pragma unroll
            for (int np = 0; np < 4; np++)
                LDSM_X4(bf[np][0], bf[np][1], bf[np][2], bf[np][3], bro + np*16*TPITCH);
            #pragma unroll
            for (int mi = 0; mi < 2; mi++)
                #pragma unroll
                for (int ni = 0; ni < 8; ni++) {
                    int np = ni >> 1;
                    uint32_t b0r = (ni & 1) ? bf[np][1] : bf[np][0];
                    uint32_t b1r = (ni & 1) ? bf[np][3] : bf[np][2];
                    MMA16816(acc[mi][ni], ah[mi], b0r, b1r);
                }
        }
    }

    // epilogue
    #pragma unroll
    for (int mi = 0; mi < 2; mi++) {
        int rA = m0 + wm*32 + mi*16 + (l >> 2);
        int rB = rA + 8;
        float pA0, pA1, pB0, pB1;
        if (MODE == 0) { pA0 = bias[rA]; pA1 = 0.0f; pB0 = bias[rB]; pB1 = 0.0f; }
        else { pA0 = g_alpha[rA]; pA1 = g_beta[rA]; pB0 = g_alpha[rB]; pB1 = g_beta[rB]; }
        #pragma unroll
        for (int ni = 0; ni < 8; ni++) {
            int col = n0 + wn*64 + ni*8 + (l & 3)*2;
            float* c = acc[mi][ni];
            if (MODE == 0) {
                *(__half2*)(Ch + (size_t)rA*NP + col) = __floats2half2_rn(c[0]+pA0, c[1]+pA0);
                *(__half2*)(Ch + (size_t)rB*NP + col) = __floats2half2_rn(c[2]+pB0, c[3]+pB0);
            } else {
                *(float2*)(Cf + (size_t)rA*NP + col) =
                    make_float2(gelu_exact(c[0]*pA0 + pA1), gelu_exact(c[1]*pA0 + pA1));
                *(float2*)(Cf + (size_t)rB*NP + col) =
                    make_float2(gelu_exact(c[2]*pB0 + pB1), gelu_exact(c[3]*pB0 + pB1));
            }
        }
    }
}

// ---------------- fused attention: logits+exp in smem, AV, rowsum ------------
__global__ void __launch_bounds__(256) k_attn() {
    int chunk = blockIdx.x, h = blockIdx.y, b = blockIdx.z;
    int tid = threadIdx.x, l = tid & 31;
    __shared__ float qs[CLSN*DHEAD];
    __shared__ float ps[CLSN*256];
    __shared__ float bsum[CLSN];
    const float scale = 0.07216878364870322f;   // 1/sqrt(192)
    for (int i = tid; i < CLSN*DHEAD; i += 256) {
        int m = i / DHEAD, d = i - m*DHEAD;
        qs[i] = g_q[(b*CLSN + m)*CDIM + h*DHEAD + d] * scale;
    }
    if (tid < CLSN) bsum[tid] = 0.0f;
    __syncthreads();
    {
        int n = chunk*256 + tid;
        const __half* kvp = g_kvh + ((size_t)b*2*CDIM + h*DHEAD)*NP + n;
        float acc[CLSN] = {};
        for (int d = 0; d < DHEAD; d++) {
            float kval = __half2float(kvp[(size_t)d * NP]);
            #pragma unroll
            for (int m = 0; m < CLSN; m++) acc[m] += qs[m*DHEAD + d] * kval;
        }
        #pragma unroll
        for (int m = 0; m < CLSN; m++) {
            float e = __expf(acc[m]);
            ps[m*256 + tid] = e;
            #pragma unroll
            for (int o = 16; o; o >>= 1) e += __shfl_xor_sync(0xFFFFFFFFu, e, o);
            if (l == 0) atomicAdd(&bsum[m], e);
        }
    }
    __syncthreads();
    if (tid < CLSN)
        atomicAdd(&g_rowsum[((size_t)(b*NHEADS + h))*CLSN + tid], bsum[tid]);
    if (tid < DHEAD) {
        const __half* vp = g_kvh + ((size_t)b*2*CDIM + CDIM + h*DHEAD + tid)*NP + chunk*256;
        float acc[CLSN] = {};
        for (int nn = 0; nn < 256; nn += 2) {
            float2 vv = __half22float2(*(const __half2*)(vp + nn));
            #pragma unroll
            for (int m = 0; m < CLSN; m++)
                acc[m] += ps[m*256 + nn]*vv.x + ps[m*256 + nn + 1]*vv.y;
        }
        #pragma unroll
        for (int m = 0; m < CLSN; m++)
            atomicAdd(&g_outflat[(b*CLSN + m)*CDIM + h*DHEAD + tid], acc[m]);
    }
}

// ---------------- out_patch = out_cls @ input_patch, split-K x2 --------------
__global__ void __launch_bounds__(256) k_opatch(const float* __restrict__ patch,
                                                const float* __restrict__ ocls) {
    int chunk = blockIdx.x, b = blockIdx.y, kz = blockIdx.z;
    int tid = threadIdx.x;
    int n = chunk*256 + tid;
    __shared__ float a_s[CLSN*96];
    float acc[CLSN] = {};
    for (int k0 = kz*384; k0 < kz*384 + 384; k0 += 96) {
        __syncthreads();
        for (int i = tid; i < CLSN*96; i += 256) {
            int m = i / 96, kk = i - m*96;
            a_s[i] = ocls[(b*CLSN + m)*CDIM + k0 + kk];
        }
        __syncthreads();
        for (int kk = 0; kk < 96; kk++) {
            float pv = patch[(size_t)b*PPB + (size_t)(k0+kk)*NP + n];
            #pragma unroll
            for (int m = 0; m < CLSN; m++) acc[m] += a_s[m*96 + kk] * pv;
        }
    }
    #pragma unroll
    for (int m = 0; m < CLSN; m++)
        atomicAdd(&g_opatch[((size_t)b*CLSN + m)*NP + n], acc[m]);
}

// ---------------- im2col transposed + fp16 -----------------------------------
__global__ void k_im2colT() {
    int i = blockIdx.x * 256 + threadIdx.x;
    int b = i / (NP*KPAD);
    int rest = i - b * NP*KPAD;
    int n = rest / KPAD, k = rest - n*KPAD;
    float val = 0.0f;
    if (k < 180) {
        int ic = k / 9, t = k - ic*9;
        int hh = (n >> 5) + t/3 - 1, ww = (n & 31) + t%3 - 1;
        if (hh >= 0 && hh < 32 && ww >= 0 && ww < 32)
            val = g_opatch[((size_t)b*CLSN + ic)*NP + hh*32 + ww];
    }
    g_ich[i] = __float2half_rn(val);
}

// ---------------- launcher ---------------------------------------------------
extern "C" void kernel_launch(void* const* d_in, const int* in_sizes, int n_in,
                              void* d_out, int out_size) {
    const float* x_cls  = (const float*)d_in[0];
    const float* patch  = (const float*)d_in[1];
    const float* ln_w   = (const float*)d_in[2];
    const float* ln_b   = (const float*)d_in[3];
    const float* nx_w   = (const float*)d_in[4];
    const float* nx_b   = (const float*)d_in[5];
    const float* Wq     = (const float*)d_in[6];
    const float* bq     = (const float*)d_in[7];
    const float* Wkv    = (const float*)d_in[8];
    const float* bkv    = (const float*)d_in[9];
    const float* Wp     = (const float*)d_in[10];
    const float* bp     = (const float*)d_in[11];
    const float* Wconv  = (const float*)d_in[12];
    const float* bconv  = (const float*)d_in[13];
    const float* bn_g   = (const float*)d_in[14];
    const float* bn_b   = (const float*)d_in[15];
    const float* bn_m   = (const float*)d_in[16];
    const float* bn_v   = (const float*)d_in[17];
    float* out_cls = (float*)d_out;
    float* y       = out_cls + ROWS*CDIM;

    static cudaStream_t s1 = nullptr, s2 = nullptr;
    static cudaEvent_t e0, e1, e2, e3, e4;
    if (!s1) {
        cudaStreamCreateWithFlags(&s1, cudaStreamNonBlocking);
        cudaStreamCreateWithFlags(&s2, cudaStreamNonBlocking);
        cudaEventCreateWithFlags(&e0, cudaEventDisableTiming);
        cudaEventCreateWithFlags(&e1, cudaEventDisableTiming);
        cudaEventCreateWithFlags(&e2, cudaEventDisableTiming);
        cudaEventCreateWithFlags(&e3, cudaEventDisableTiming);
        cudaEventCreateWithFlags(&e4, cudaEventDisableTiming);
        cudaFuncSetAttribute(gemm_mma<0>, cudaFuncAttributeMaxDynamicSharedMemorySize, SMEMB);
        cudaFuncSetAttribute(gemm_mma<1>, cudaFuncAttributeMaxDynamicSharedMemorySize, SMEMB);
    }
    cudaStream_t s0 = 0;

    // ---- minimal fork point: tiny zero on critical path ----
    k_zero_small<<<5, 256, 0, s0>>>();
    cudaEventRecord(e0, s0);

    // side chain 1: cls LN + q projection (direct write, no zero needed)
    cudaStreamWaitEvent(s1, e0, 0);
    k_lncls<<<ROWS, 256, 0, s1>>>(x_cls, ln_w, ln_b);
    gemm_nt<0><<<dim3(12, 5), 256, 0, s1>>>(Wq, bq, nullptr, nullptr);
    cudaEventRecord(e1, s1);

    // side chain 2: bulk zero + weight preps (hidden under main chain)
    cudaStreamWaitEvent(s2, e0, 0);
    k_zero_big<<<1280, 256, 0, s2>>>(out_cls);
    cudaEventRecord(e4, s2);
    k_prep_wkv<<<(2*CDIM*CDIM)/256, 256, 0, s2>>>(Wkv);
    cudaEventRecord(e2, s2);
    k_prepconv<<<(CDIM*KPAD + 255)/256, 256, 0, s2>>>(Wconv, bconv, bn_g, bn_b, bn_m, bn_v);
    cudaEventRecord(e3, s2);

    // main chain (critical path)
    k_psum<<<dim3(48, BATCH), 256, 0, s0>>>(patch);
    k_nxT<<<dim3(32, 24, BATCH), 256, 0, s0>>>(patch, nx_w, nx_b);
    cudaStreamWaitEvent(s0, e2, 0);
    gemm_mma<0><<<dim3(8, 12, BATCH), 256, SMEMB, s0>>>(bkv, nullptr);
    cudaStreamWaitEvent(s0, e1, 0);
    cudaStreamWaitEvent(s0, e4, 0);
    k_attn<<<dim3(4, NHEADS, BATCH), 256, 0, s0>>>();
    gemm_nt<1><<<dim3(12, 5, 2), 256, 0, s0>>>(Wp, bp, x_cls, out_cls);
    k_opatch<<<dim3(4, BATCH, 2), 256, 0, s0>>>(patch, out_cls);
    k_im2colT<<<(BATCH*NP*KPAD)/256, 256, 0, s0>>>();
    cudaStreamWaitEvent(s0, e3, 0);
    gemm_mma<1><<<dim3(8, 6, BATCH), 256, SMEMB, s0>>>(nullptr, y);
}

// round 15
// speedup vs baseline: 1.1822x; 1.1136x over previous
#include <cuda_runtime.h>
#include <cuda_fp16.h>
#include <cstdint>
#include <math.h>

#define EPSV 1e-5f
#define BATCH 16
#define CLSN 20
#define CDIM 768
#define NHEADS 4
#define DHEAD 192
#define NP 1024
#define ROWS (BATCH*CLSN)
#define PPB (CDIM*NP)
#define KPAD 192

// ---------------- scratch ----------------------------------------------------
__device__ float g_xln[ROWS*CDIM];
__device__ float g_q[ROWS*CDIM];
__device__ float g_sums[32];
__device__ float g_rowsum[BATCH*NHEADS*CLSN];
__device__ float g_outflat[ROWS*CDIM];
__device__ float g_opatch[BATCH*CLSN*NP];
__device__ float g_alpha[CDIM];
__device__ float g_beta[CDIM];
__device__ __align__(128) __half g_kvh[BATCH*2*CDIM*NP];  // 50 MB fp16
__device__ __align__(128) __half g_Wkvh[2*CDIM*CDIM];
__device__ __align__(128) __half g_nxTh[BATCH*NP*CDIM];   // [b][n][c]
__device__ __align__(128) __half g_W2h[CDIM*KPAD];
__device__ __align__(128) __half g_ich[BATCH*NP*KPAD];    // [b][n][k]

__device__ __forceinline__ float gelu_exact(float x) {
    return 0.5f * x * (1.0f + erff(x * 0.70710678118654752440f));
}
__device__ __forceinline__ uint32_t s2u(const void* p) {
    uint32_t a;
    asm("{ .reg .u64 t; cvta.to.shared.u64 t, %1; cvt.u32.u64 %0, t; }" : "=r"(a) : "l"(p));
    return a;
}
__device__ __forceinline__ void cp16(uint32_t dst, const void* src) {
    asm volatile("cp.async.cg.shared.global [%0], [%1], 16;" :: "r"(dst), "l"(src));
}
#define CP_COMMIT() asm volatile("cp.async.commit_group;" ::: "memory")
#define LDSM_X4(r0,r1,r2,r3,a) \
    asm volatile("ldmatrix.sync.aligned.m8n8.x4.shared.b16 {%0,%1,%2,%3}, [%4];" \
                 : "=r"(r0), "=r"(r1), "=r"(r2), "=r"(r3) : "r"(a))
#define MMA16816(c, a, b0, b1) \
    asm volatile("mma.sync.aligned.m16n8k16.row.col.f32.f16.f16.f32 " \
                 "{%0,%1,%2,%3}, {%4,%5,%6,%7}, {%8,%9}, {%0,%1,%2,%3};" \
                 : "+f"((c)[0]), "+f"((c)[1]), "+f"((c)[2]), "+f"((c)[3]) \
                 : "r"((a)[0]), "r"((a)[1]), "r"((a)[2]), "r"((a)[3]), "r"(b0), "r"(b1))

// ---------------- zeroing: small (critical path) + big (side stream) ---------
__global__ void k_zero_small() {
    int i = threadIdx.x + blockIdx.x * 256;
    if (i < 32) g_sums[i] = 0.0f;
    if (i < BATCH*NHEADS*CLSN) g_rowsum[i] = 0.0f;
}
__global__ void k_zero_big(float* __restrict__ out_cls) {
    int i = blockIdx.x * 256 + threadIdx.x;
    if (i < ROWS*CDIM) { g_outflat[i] = 0.0f; out_cls[i] = 0.0f; }
    if (i < BATCH*CLSN*NP) g_opatch[i] = 0.0f;
}

__global__ void k_lncls(const float* __restrict__ x, const float* __restrict__ w,
                        const float* __restrict__ bb) {
    int r = blockIdx.x, tid = threadIdx.x;
    const float* xr = x + r * CDIM;
    float v0 = xr[tid], v1 = xr[tid+256], v2 = xr[tid+512];
    __shared__ float red[256];
    __shared__ float s_mu, s_rs;
    red[tid] = v0 + v1 + v2; __syncthreads();
    for (int o = 128; o; o >>= 1) { if (tid < o) red[tid] += red[tid+o]; __syncthreads(); }
    if (tid == 0) s_mu = red[0] * (1.0f/768.0f);
    __syncthreads();
    float mu = s_mu;
    float d0 = v0-mu, d1 = v1-mu, d2 = v2-mu;
    red[tid] = d0*d0 + d1*d1 + d2*d2; __syncthreads();
    for (int o = 128; o; o >>= 1) { if (tid < o) red[tid] += red[tid+o]; __syncthreads(); }
    if (tid == 0) s_rs = rsqrtf(red[0] * (1.0f/768.0f) + EPSV);
    __syncthreads();
    float rs = s_rs;
    float* o = g_xln + r * CDIM;
    o[tid]     = d0*rs*w[tid]     + bb[tid];
    o[tid+256] = d1*rs*w[tid+256] + bb[tid+256];
    o[tid+512] = d2*rs*w[tid+512] + bb[tid+512];
}

// vectorized per-batch sums
__global__ void k_psum(const float* __restrict__ x) {
    int b = blockIdx.y, tid = threadIdx.x;
    const float4* p = (const float4*)(x + (size_t)b * PPB + blockIdx.x * 16384);
    float s = 0.0f, q = 0.0f;
    #pragma unroll 4
    for (int i = 0; i < 16; i++) {
        float4 v = p[i*256 + tid];
        s += v.x + v.y + v.z + v.w;
        q += v.x*v.x + v.y*v.y + v.z*v.z + v.w*v.w;
    }
    __shared__ float rs[256], rq[256];
    rs[tid] = s; rq[tid] = q; __syncthreads();
    for (int o = 128; o; o >>= 1) {
        if (tid < o) { rs[tid] += rs[tid+o]; rq[tid] += rq[tid+o]; }
        __syncthreads();
    }
    if (tid == 0) { atomicAdd(&g_sums[b], rs[0]); atomicAdd(&g_sums[16+b], rq[0]); }
}

// normalize + transpose + fp16:  g_nxTh[b][n][c]
__global__ void __launch_bounds__(256) k_nxT(const float* __restrict__ x,
                                             const float* __restrict__ w,
                                             const float* __restrict__ bb) {
    __shared__ float t[32][33];
    int b = blockIdx.z, c0 = blockIdx.y*32, n0 = blockIdx.x*32;
    int tx = threadIdx.x & 31, ty = threadIdx.x >> 5;
    float mu  = g_sums[b]    * (1.0f/786432.0f);
    float var = g_sums[16+b] * (1.0f/786432.0f) - mu*mu;
    float rv = rsqrtf(var + EPSV);
    #pragma unroll
    for (int i = 0; i < 4; i++) {
        int c = c0 + ty + i*8;
        float v = x[(size_t)b*PPB + (size_t)c*NP + n0 + tx];
        t[tx][ty + i*8] = (v - mu)*rv*w[c] + bb[c];
    }
    __syncthreads();
    #pragma unroll
    for (int i = 0; i < 4; i++) {
        int n = n0 + ty + i*8;
        float v = t[ty + i*8][tx];
        g_nxTh[((size_t)b*NP + n)*CDIM + c0 + tx] = __float2half_rn(v);
    }
}

__global__ void k_prep_wkv(const float* __restrict__ W) {
    int i = blockIdx.x * 256 + threadIdx.x;
    if (i < 2*CDIM*CDIM) g_Wkvh[i] = __float2half_rn(W[i]);
}

__global__ void k_prepconv(const float* __restrict__ Wc, const float* __restrict__ bc,
                           const float* __restrict__ g,  const float* __restrict__ bt,
                           const float* __restrict__ mn, const float* __restrict__ vr) {
    int i = blockIdx.x * 256 + threadIdx.x;
    if (i < CDIM*KPAD) {
        int o = i / KPAD, k = i - o*KPAD;
        g_W2h[i] = __float2half_rn((k < 180) ? Wc[o*180 + k] : 0.0f);
    }
    if (i < CDIM) {
        float al = g[i] * rsqrtf(vr[i] + EPSV);
        g_alpha[i] = al;
        g_beta[i]  = (bc[i] - mn[i]) * al + bt[i];
    }
}

// ---------------- small NT GEMM --------------------------------------------
// MODE 0: q proj, single pass, direct write. MODE 1: out proj, split-K x4,
// atomics; A scaled by 1/rowsum on the fly.
template<int MODE>
__global__ void __launch_bounds__(256) gemm_nt(const float* __restrict__ Bw,
                                               const float* __restrict__ bias,
                                               const float* __restrict__ res,
                                               float* __restrict__ Cext) {
    const float* A = (MODE == 0) ? g_xln : g_outflat;
    float* C = (MODE == 0) ? g_q : Cext;
    __shared__ float As[16*68];
    __shared__ float Bs[16*68];
    int m0 = blockIdx.y * 64, n0 = blockIdx.x * 64, kz = (MODE == 0) ? 0 : blockIdx.z;
    const int KB = (MODE == 0) ? 768 : 192;
    int tid = threadIdx.x, tx = tid & 15, ty = tid >> 4;
    float acc[4][4] = {};
    int row = tid >> 2, kq = tid & 3;
    int m = m0 + row;
    int bb_ = m / CLSN, mc = m - bb_*CLSN;
    for (int k0 = kz*192; k0 < kz*192 + KB; k0 += 16) {
        float4 va = *(const float4*)(A  + (size_t)m*768 + k0 + kq*4);
        float4 vb = *(const float4*)(Bw + (size_t)(n0+row)*768 + k0 + kq*4);
        if (MODE == 1) {
            int h = (k0 + kq*4) / DHEAD;
            float inv = 1.0f / g_rowsum[((size_t)(bb_*NHEADS + h))*CLSN + mc];
            va.x *= inv; va.y *= inv; va.z *= inv; va.w *= inv;
        }
        As[(kq*4+0)*68+row] = va.x; As[(kq*4+1)*68+row] = va.y;
        As[(kq*4+2)*68+row] = va.z; As[(kq*4+3)*68+row] = va.w;
        Bs[(kq*4+0)*68+row] = vb.x; Bs[(kq*4+1)*68+row] = vb.y;
        Bs[(kq*4+2)*68+row] = vb.z; Bs[(kq*4+3)*68+row] = vb.w;
        __syncthreads();
        #pragma unroll
        for (int k = 0; k < 16; k++) {
            float4 a4 = *(const float4*)(&As[k*68 + ty*4]);
            float4 b4 = *(const float4*)(&Bs[k*68 + tx*4]);
            float am[4] = {a4.x, a4.y, a4.z, a4.w};
            float bn[4] = {b4.x, b4.y, b4.z, b4.w};
            #pragma unroll
            for (int i = 0; i < 4; i++)
                #pragma unroll
                for (int j = 0; j < 4; j++) acc[i][j] += am[i]*bn[j];
        }
        __syncthreads();
    }
    #pragma unroll
    for (int i = 0; i < 4; i++) {
        int mm = m0 + ty*4 + i;
        #pragma unroll
        for (int j = 0; j < 4; j++) {
            int n = n0 + tx*4 + j;
            if (MODE == 0) {
                C[mm*768 + n] = acc[i][j] + bias[n];
            } else {
                float add = 0.0f;
                if (kz == 0) add = bias[n] + res[mm*768 + n];
                atomicAdd(&C[mm*768 + n], acc[i][j] + add);
            }
        }
    }
}

// ---------------- mma.sync fp16 GEMM, k32 slabs ------------------------------
#define TPITCH 80
#define TBYTES (128*TPITCH)
#define STAGEB (2*TBYTES)
#define NSTG 3
#define SMEMB (NSTG*STAGEB)          /* 61440 */
template<int MODE>
__global__ void __launch_bounds__(256, 2) gemm_mma(const float* __restrict__ bias,
                                                   float* __restrict__ Cout) {
    const int K  = (MODE == 0) ? 768 : KPAD;
    const int NS = K / 32;
    extern __shared__ __align__(1024) char sm[];
    uint32_t sb = s2u(sm);
    int tid = threadIdx.x;
    int w = tid >> 5, l = tid & 31;
    int wm = w >> 1, wn = w & 1;
    int b = blockIdx.z;
    int m0 = blockIdx.y * 128, n0 = blockIdx.x * 128;

    const __half* Ah = (MODE == 0) ? g_Wkvh : g_W2h;
    const __half* Bh = ((MODE == 0) ? g_nxTh : g_ich) + (size_t)b * NP * K;
    __half* Ch = g_kvh + (size_t)b * 2*CDIM*NP;
    float* Cf  = Cout + (size_t)b * CDIM*NP;

    float acc[2][8][4] = {};

    int r0 = tid >> 2, q0 = tid & 3;
    int r1 = ((tid + 256) >> 2), q1 = q0;

    auto load_stage = [&](int s) {
        uint32_t st = sb + (s % NSTG) * STAGEB;
        int k0 = s * 32;
        cp16(st + r0*TPITCH + q0*16,          Ah + (size_t)(m0+r0)*K + k0 + q0*8);
        cp16(st + r1*TPITCH + q1*16,          Ah + (size_t)(m0+r1)*K + k0 + q1*8);
        cp16(st + TBYTES + r0*TPITCH + q0*16, Bh + (size_t)(n0+r0)*K + k0 + q0*8);
        cp16(st + TBYTES + r1*TPITCH + q1*16, Bh + (size_t)(n0+r1)*K + k0 + q1*8);
        CP_COMMIT();
    };
    load_stage(0);
    load_stage(1);

    int lrow = (l & 7) + ((l >> 3) & 1) * 8;
    int lko  = (l >> 4) * 16;

    for (int s = 0; s < NS; s++) {
        if (s + 1 < NS) asm volatile("cp.async.wait_group 1;" ::: "memory");
        else            asm volatile("cp.async.wait_group 0;" ::: "memory");
        __syncthreads();
        if (s + 2 < NS) load_stage(s + 2);
        uint32_t st = sb + (s % NSTG) * STAGEB;
        #pragma unroll
        for (int kk = 0; kk < 2; kk++) {
            uint32_t aro = st + (wm*32 + lrow)*TPITCH + lko + kk*32;
            uint32_t bro = st + TBYTES + (wn*64 + lrow)*TPITCH + lko + kk*32;
            uint32_t ah[2][4], bf[4][4];
            #pragma unroll
            for (int mi = 0; mi < 2; mi++)
                LDSM_X4(ah[mi][0], ah[mi][1], ah[mi][2], ah[mi][3], aro + mi*16*TPITCH);
            #pragma unroll
            for (int np = 0; np < 4; np++)
                LDSM_X4(bf[np][0], bf[np][1], bf[np][2], bf[np][3], bro + np*16*TPITCH);
            #pragma unroll
            for (int mi = 0; mi < 2; mi++)
                #pragma unroll
                for (int ni = 0; ni < 8; ni++) {
                    int np = ni >> 1;
                    uint32_t b0r = (ni & 1) ? bf[np][1] : bf[np][0];
                    uint32_t b1r = (ni & 1) ? bf[np][3] : bf[np][2];
                    MMA16816(acc[mi][ni], ah[mi], b0r, b1r);
                }
        }
    }

    // epilogue
    #pragma unroll
    for (int mi = 0; mi < 2; mi++) {
        int rA = m0 + wm*32 + mi*16 + (l >> 2);
        int rB = rA + 8;
        float pA0, pA1, pB0, pB1;
        if (MODE == 0) { pA0 = bias[rA]; pA1 = 0.0f; pB0 = bias[rB]; pB1 = 0.0f; }
        else { pA0 = g_alpha[rA]; pA1 = g_beta[rA]; pB0 = g_alpha[rB]; pB1 = g_beta[rB]; }
        #pragma unroll
        for (int ni = 0; ni < 8; ni++) {
            int col = n0 + wn*64 + ni*8 + (l & 3)*2;
            float* c = acc[mi][ni];
            if (MODE == 0) {
                *(__half2*)(Ch + (size_t)rA*NP + col) = __floats2half2_rn(c[0]+pA0, c[1]+pA0);
                *(__half2*)(Ch + (size_t)rB*NP + col) = __floats2half2_rn(c[2]+pB0, c[3]+pB0);
            } else {
                *(float2*)(Cf + (size_t)rA*NP + col) =
                    make_float2(gelu_exact(c[0]*pA0 + pA1), gelu_exact(c[1]*pA0 + pA1));
                *(float2*)(Cf + (size_t)rB*NP + col) =
                    make_float2(gelu_exact(c[2]*pB0 + pB1), gelu_exact(c[3]*pB0 + pB1));
            }
        }
    }
}

// ---------------- fused attention: logits+exp in smem, AV, rowsum ------------
__global__ void __launch_bounds__(256) k_attn() {
    int chunk = blockIdx.x, h = blockIdx.y, b = blockIdx.z;
    int tid = threadIdx.x, l = tid & 31;
    __shared__ float qs[CLSN*DHEAD];
    __shared__ float ps[CLSN*256];
    __shared__ float bsum[CLSN];
    const float scale = 0.07216878364870322f;   // 1/sqrt(192)
    for (int i = tid; i < CLSN*DHEAD; i += 256) {
        int m = i / DHEAD, d = i - m*DHEAD;
        qs[i] = g_q[(b*CLSN + m)*CDIM + h*DHEAD + d] * scale;
    }
    if (tid < CLSN) bsum[tid] = 0.0f;
    __syncthreads();
    {
        int n = chunk*256 + tid;
        const __half* kvp = g_kvh + ((size_t)b*2*CDIM + h*DHEAD)*NP + n;
        float acc[CLSN] = {};
        for (int d = 0; d < DHEAD; d++) {
            float kval = __half2float(kvp[(size_t)d * NP]);
            #pragma unroll
            for (int m = 0; m < CLSN; m++) acc[m] += qs[m*DHEAD + d] * kval;
        }
        #pragma unroll
        for (int m = 0; m < CLSN; m++) {
            float e = __expf(acc[m]);
            ps[m*256 + tid] = e;
            #pragma unroll
            for (int o = 16; o; o >>= 1) e += __shfl_xor_sync(0xFFFFFFFFu, e, o);
            if (l == 0) atomicAdd(&bsum[m], e);
        }
    }
    __syncthreads();
    if (tid < CLSN)
        atomicAdd(&g_rowsum[((size_t)(b*NHEADS + h))*CLSN + tid], bsum[tid]);
    if (tid < DHEAD) {
        const __half* vp = g_kvh + ((size_t)b*2*CDIM + CDIM + h*DHEAD + tid)*NP + chunk*256;
        float acc[CLSN] = {};
        for (int nn = 0; nn < 256; nn += 2) {
            float2 vv = __half22float2(*(const __half2*)(vp + nn));
            #pragma unroll
            for (int m = 0; m < CLSN; m++)
                acc[m] += ps[m*256 + nn]*vv.x + ps[m*256 + nn + 1]*vv.y;
        }
        #pragma unroll
        for (int m = 0; m < CLSN; m++)
            atomicAdd(&g_outflat[(b*CLSN + m)*CDIM + h*DHEAD + tid], acc[m]);
    }
}

// ---------------- out_patch = out_cls @ input_patch, split-K x4 --------------
__global__ void __launch_bounds__(256) k_opatch(const float* __restrict__ patch,
                                                const float* __restrict__ ocls) {
    int chunk = blockIdx.x, b = blockIdx.y, kz = blockIdx.z;
    int tid = threadIdx.x;
    int n = chunk*256 + tid;
    __shared__ float a_s[CLSN*96];
    float acc[CLSN] = {};
    for (int k0 = kz*192; k0 < kz*192 + 192; k0 += 96) {
        __syncthreads();
        for (int i = tid; i < CLSN*96; i += 256) {
            int m = i / 96, kk = i - m*96;
            a_s[i] = ocls[(b*CLSN + m)*CDIM + k0 + kk];
        }
        __syncthreads();
        for (int kk = 0; kk < 96; kk++) {
            float pv = patch[(size_t)b*PPB + (size_t)(k0+kk)*NP + n];
            #pragma unroll
            for (int m = 0; m < CLSN; m++) acc[m] += a_s[m*96 + kk] * pv;
        }
    }
    #pragma unroll
    for (int m = 0; m < CLSN; m++)
        atomicAdd(&g_opatch[((size_t)b*CLSN + m)*NP + n], acc[m]);
}

// ---------------- im2col transposed + fp16, 4-wide ---------------------------
__global__ void k_im2colT() {
    int i4 = blockIdx.x * 256 + threadIdx.x;    // over BATCH*NP*(KPAD/4)
    int b = i4 / (NP*(KPAD/4));
    int rest = i4 - b * NP*(KPAD/4);
    int n = rest / (KPAD/4), kq = (rest - n*(KPAD/4)) * 4;
    int hh0 = n >> 5, ww0 = n & 31;
    __half vals[4];
    #pragma unroll
    for (int j = 0; j < 4; j++) {
        int k = kq + j;
        float val = 0.0f;
        if (k < 180) {
            int ic = k / 9, t = k - ic*9;
            int hh = hh0 + t/3 - 1, ww = ww0 + t%3 - 1;
            if (hh >= 0 && hh < 32 && ww >= 0 && ww < 32)
                val = g_opatch[((size_t)b*CLSN + ic)*NP + hh*32 + ww];
        }
        vals[j] = __float2half_rn(val);
    }
    *(uint2*)(g_ich + (size_t)i4*4) = *(uint2*)vals;
}

// ---------------- launcher ---------------------------------------------------
extern "C" void kernel_launch(void* const* d_in, const int* in_sizes, int n_in,
                              void* d_out, int out_size) {
    const float* x_cls  = (const float*)d_in[0];
    const float* patch  = (const float*)d_in[1];
    const float* ln_w   = (const float*)d_in[2];
    const float* ln_b   = (const float*)d_in[3];
    const float* nx_w   = (const float*)d_in[4];
    const float* nx_b   = (const float*)d_in[5];
    const float* Wq     = (const float*)d_in[6];
    const float* bq     = (const float*)d_in[7];
    const float* Wkv    = (const float*)d_in[8];
    const float* bkv    = (const float*)d_in[9];
    const float* Wp     = (const float*)d_in[10];
    const float* bp     = (const float*)d_in[11];
    const float* Wconv  = (const float*)d_in[12];
    const float* bconv  = (const float*)d_in[13];
    const float* bn_g   = (const float*)d_in[14];
    const float* bn_b   = (const float*)d_in[15];
    const float* bn_m   = (const float*)d_in[16];
    const float* bn_v   = (const float*)d_in[17];
    float* out_cls = (float*)d_out;
    float* y       = out_cls + ROWS*CDIM;

    static cudaStream_t s1 = nullptr, s2 = nullptr;
    static cudaEvent_t e0, e1, e2, e3, e4;
    if (!s1) {
        cudaStreamCreateWithFlags(&s1, cudaStreamNonBlocking);
        cudaStreamCreateWithFlags(&s2, cudaStreamNonBlocking);
        cudaEventCreateWithFlags(&e0, cudaEventDisableTiming);
        cudaEventCreateWithFlags(&e1, cudaEventDisableTiming);
        cudaEventCreateWithFlags(&e2, cudaEventDisableTiming);
        cudaEventCreateWithFlags(&e3, cudaEventDisableTiming);
        cudaEventCreateWithFlags(&e4, cudaEventDisableTiming);
        cudaFuncSetAttribute(gemm_mma<0>, cudaFuncAttributeMaxDynamicSharedMemorySize, SMEMB);
        cudaFuncSetAttribute(gemm_mma<1>, cudaFuncAttributeMaxDynamicSharedMemorySize, SMEMB);
    }
    cudaStream_t s0 = 0;

    // ---- minimal fork point: tiny zero on critical path ----
    k_zero_small<<<5, 256, 0, s0>>>();
    cudaEventRecord(e0, s0);

    // side chain 1: cls LN + q projection
    cudaStreamWaitEvent(s1, e0, 0);
    k_lncls<<<ROWS, 256, 0, s1>>>(x_cls, ln_w, ln_b);
    gemm_nt<0><<<dim3(12, 5), 256, 0, s1>>>(Wq, bq, nullptr, nullptr);
    cudaEventRecord(e1, s1);

    // side chain 2: bulk zero + weight preps
    cudaStreamWaitEvent(s2, e0, 0);
    k_zero_big<<<1280, 256, 0, s2>>>(out_cls);
    cudaEventRecord(e4, s2);
    k_prep_wkv<<<(2*CDIM*CDIM)/256, 256, 0, s2>>>(Wkv);
    cudaEventRecord(e2, s2);
    k_prepconv<<<(CDIM*KPAD + 255)/256, 256, 0, s2>>>(Wconv, bconv, bn_g, bn_b, bn_m, bn_v);
    cudaEventRecord(e3, s2);

    // main chain (critical path)
    k_psum<<<dim3(48, BATCH), 256, 0, s0>>>(patch);
    k_nxT<<<dim3(32, 24, BATCH), 256, 0, s0>>>(patch, nx_w, nx_b);
    cudaStreamWaitEvent(s0, e2, 0);
    gemm_mma<0><<<dim3(8, 12, BATCH), 256, SMEMB, s0>>>(bkv, nullptr);
    cudaStreamWaitEvent(s0, e1, 0);
    cudaStreamWaitEvent(s0, e4, 0);
    k_attn<<<dim3(4, NHEADS, BATCH), 256, 0, s0>>>();
    gemm_nt<1><<<dim3(12, 5, 4), 256, 0, s0>>>(Wp, bp, x_cls, out_cls);
    k_opatch<<<dim3(4, BATCH, 4), 256, 0, s0>>>(patch, out_cls);
    k_im2colT<<<(BATCH*NP*(KPAD/4))/256, 256, 0, s0>>>();
    cudaStreamWaitEvent(s0, e3, 0);
    gemm_mma<1><<<dim3(8, 6, BATCH), 256, SMEMB, s0>>>(nullptr, y);
}

// round 16
// speedup vs baseline: 1.1994x; 1.0146x over previous
#include <cuda_runtime.h>
#include <cuda_fp16.h>
#include <cstdint>
#include <math.h>

#define EPSV 1e-5f
#define BATCH 16
#define CLSN 20
#define CDIM 768
#define NHEADS 4
#define DHEAD 192
#define NP 1024
#define ROWS (BATCH*CLSN)
#define PPB (CDIM*NP)
#define KPAD 192

// ---------------- scratch ----------------------------------------------------
__device__ float g_xln[ROWS*CDIM];
__device__ float g_q[ROWS*CDIM];
__device__ float g_sums[32];
__device__ float g_rowsum[BATCH*NHEADS*CLSN];
__device__ float g_outflat[ROWS*CDIM];
__device__ float g_opatch[BATCH*CLSN*NP];
__device__ float g_alpha[CDIM];
__device__ float g_beta[CDIM];
__device__ __align__(128) __half g_kvh[BATCH*2*CDIM*NP];  // 50 MB fp16
__device__ __align__(128) __half g_Wkvh[2*CDIM*CDIM];
__device__ __align__(128) __half g_nxTh[BATCH*NP*CDIM];   // [b][n][c]
__device__ __align__(128) __half g_W2h[CDIM*KPAD];
__device__ __align__(128) __half g_ich[BATCH*NP*KPAD];    // [b][n][k]

__device__ __forceinline__ float gelu_exact(float x) {
    return 0.5f * x * (1.0f + erff(x * 0.70710678118654752440f));
}
__device__ __forceinline__ uint32_t s2u(const void* p) {
    uint32_t a;
    asm("{ .reg .u64 t; cvta.to.shared.u64 t, %1; cvt.u32.u64 %0, t; }" : "=r"(a) : "l"(p));
    return a;
}
__device__ __forceinline__ void cp16(uint32_t dst, const void* src) {
    asm volatile("cp.async.cg.shared.global [%0], [%1], 16;" :: "r"(dst), "l"(src));
}
#define CP_COMMIT() asm volatile("cp.async.commit_group;" ::: "memory")
#define LDSM_X4(r0,r1,r2,r3,a) \
    asm volatile("ldmatrix.sync.aligned.m8n8.x4.shared.b16 {%0,%1,%2,%3}, [%4];" \
                 : "=r"(r0), "=r"(r1), "=r"(r2), "=r"(r3) : "r"(a))
#define MMA16816(c, a, b0, b1) \
    asm volatile("mma.sync.aligned.m16n8k16.row.col.f32.f16.f16.f32 " \
                 "{%0,%1,%2,%3}, {%4,%5,%6,%7}, {%8,%9}, {%0,%1,%2,%3};" \
                 : "+f"((c)[0]), "+f"((c)[1]), "+f"((c)[2]), "+f"((c)[3]) \
                 : "r"((a)[0]), "r"((a)[1]), "r"((a)[2]), "r"((a)[3]), "r"(b0), "r"(b1))

// ---------------- zeroing ----------------------------------------------------
__global__ void k_zero_small() {
    int i = threadIdx.x + blockIdx.x * 256;
    if (i < 32) g_sums[i] = 0.0f;
    if (i < BATCH*NHEADS*CLSN) g_rowsum[i] = 0.0f;
}
__global__ void k_zero_big(float* __restrict__ out_cls) {
    int i = blockIdx.x * 256 + threadIdx.x;
    if (i < ROWS*CDIM) { g_outflat[i] = 0.0f; out_cls[i] = 0.0f; }
    if (i < BATCH*CLSN*NP) g_opatch[i] = 0.0f;
}

__global__ void k_lncls(const float* __restrict__ x, const float* __restrict__ w,
                        const float* __restrict__ bb) {
    int r = blockIdx.x, tid = threadIdx.x;
    const float* xr = x + r * CDIM;
    float v0 = xr[tid], v1 = xr[tid+256], v2 = xr[tid+512];
    __shared__ float red[256];
    __shared__ float s_mu, s_rs;
    red[tid] = v0 + v1 + v2; __syncthreads();
    for (int o = 128; o; o >>= 1) { if (tid < o) red[tid] += red[tid+o]; __syncthreads(); }
    if (tid == 0) s_mu = red[0] * (1.0f/768.0f);
    __syncthreads();
    float mu = s_mu;
    float d0 = v0-mu, d1 = v1-mu, d2 = v2-mu;
    red[tid] = d0*d0 + d1*d1 + d2*d2; __syncthreads();
    for (int o = 128; o; o >>= 1) { if (tid < o) red[tid] += red[tid+o]; __syncthreads(); }
    if (tid == 0) s_rs = rsqrtf(red[0] * (1.0f/768.0f) + EPSV);
    __syncthreads();
    float rs = s_rs;
    float* o = g_xln + r * CDIM;
    o[tid]     = d0*rs*w[tid]     + bb[tid];
    o[tid+256] = d1*rs*w[tid+256] + bb[tid+256];
    o[tid+512] = d2*rs*w[tid+512] + bb[tid+512];
}

// vectorized per-batch sums
__global__ void k_psum(const float* __restrict__ x) {
    int b = blockIdx.y, tid = threadIdx.x;
    const float4* p = (const float4*)(x + (size_t)b * PPB + blockIdx.x * 16384);
    float s = 0.0f, q = 0.0f;
    #pragma unroll 4
    for (int i = 0; i < 16; i++) {
        float4 v = p[i*256 + tid];
        s += v.x + v.y + v.z + v.w;
        q += v.x*v.x + v.y*v.y + v.z*v.z + v.w*v.w;
    }
    __shared__ float rs[256], rq[256];
    rs[tid] = s; rq[tid] = q; __syncthreads();
    for (int o = 128; o; o >>= 1) {
        if (tid < o) { rs[tid] += rs[tid+o]; rq[tid] += rq[tid+o]; }
        __syncthreads();
    }
    if (tid == 0) { atomicAdd(&g_sums[b], rs[0]); atomicAdd(&g_sums[16+b], rq[0]); }
}

// normalize + transpose + fp16:  g_nxTh[b][n][c].  32n x 64c tiles, half2 out.
__global__ void __launch_bounds__(256) k_nxT(const float* __restrict__ x,
                                             const float* __restrict__ w,
                                             const float* __restrict__ bb) {
    __shared__ float t[32][72];                  // [n-local][c-local], pad 72
    int b = blockIdx.z, c0 = blockIdx.y*64, n0 = blockIdx.x*32;
    int tx = threadIdx.x & 31, ty = threadIdx.x >> 5;
    float mu  = g_sums[b]    * (1.0f/786432.0f);
    float var = g_sums[16+b] * (1.0f/786432.0f) - mu*mu;
    float rv = rsqrtf(var + EPSV);
    #pragma unroll
    for (int i = 0; i < 8; i++) {
        int c = c0 + ty + i*8;
        float v = x[(size_t)b*PPB + (size_t)c*NP + n0 + tx];
        t[tx][ty + i*8] = (v - mu)*rv*w[c] + bb[c];
    }
    __syncthreads();
    #pragma unroll
    for (int i = 0; i < 4; i++) {
        int n = n0 + ty + i*8;
        float v0 = t[ty + i*8][tx*2], v1 = t[ty + i*8][tx*2 + 1];
        *(__half2*)(g_nxTh + ((size_t)b*NP + n)*CDIM + c0 + tx*2) =
            __floats2half2_rn(v0, v1);
    }
}

__global__ void k_prep_wkv(const float* __restrict__ W) {
    int i = blockIdx.x * 256 + threadIdx.x;
    if (i < 2*CDIM*CDIM) g_Wkvh[i] = __float2half_rn(W[i]);
}

__global__ void k_prepconv(const float* __restrict__ Wc, const float* __restrict__ bc,
                           const float* __restrict__ g,  const float* __restrict__ bt,
                           const float* __restrict__ mn, const float* __restrict__ vr) {
    int i = blockIdx.x * 256 + threadIdx.x;
    if (i < CDIM*KPAD) {
        int o = i / KPAD, k = i - o*KPAD;
        g_W2h[i] = __float2half_rn((k < 180) ? Wc[o*180 + k] : 0.0f);
    }
    if (i < CDIM) {
        float al = g[i] * rsqrtf(vr[i] + EPSV);
        g_alpha[i] = al;
        g_beta[i]  = (bc[i] - mn[i]) * al + bt[i];
    }
}

// ---------------- small NT GEMM --------------------------------------------
// MODE 0: q proj, single pass, direct write. MODE 1: out proj, split-K x8.
template<int MODE>
__global__ void __launch_bounds__(256) gemm_nt(const float* __restrict__ Bw,
                                               const float* __restrict__ bias,
                                               const float* __restrict__ res,
                                               float* __restrict__ Cext) {
    const float* A = (MODE == 0) ? g_xln : g_outflat;
    float* C = (MODE == 0) ? g_q : Cext;
    __shared__ float As[16*68];
    __shared__ float Bs[16*68];
    int m0 = blockIdx.y * 64, n0 = blockIdx.x * 64, kz = (MODE == 0) ? 0 : blockIdx.z;
    const int KB = (MODE == 0) ? 768 : 96;
    int tid = threadIdx.x, tx = tid & 15, ty = tid >> 4;
    float acc[4][4] = {};
    int row = tid >> 2, kq = tid & 3;
    int m = m0 + row;
    int bb_ = m / CLSN, mc = m - bb_*CLSN;
    for (int k0 = kz*96; k0 < kz*96 + KB; k0 += 16) {
        float4 va = *(const float4*)(A  + (size_t)m*768 + k0 + kq*4);
        float4 vb = *(const float4*)(Bw + (size_t)(n0+row)*768 + k0 + kq*4);
        if (MODE == 1) {
            int h = (k0 + kq*4) / DHEAD;
            float inv = 1.0f / g_rowsum[((size_t)(bb_*NHEADS + h))*CLSN + mc];
            va.x *= inv; va.y *= inv; va.z *= inv; va.w *= inv;
        }
        As[(kq*4+0)*68+row] = va.x; As[(kq*4+1)*68+row] = va.y;
        As[(kq*4+2)*68+row] = va.z; As[(kq*4+3)*68+row] = va.w;
        Bs[(kq*4+0)*68+row] = vb.x; Bs[(kq*4+1)*68+row] = vb.y;
        Bs[(kq*4+2)*68+row] = vb.z; Bs[(kq*4+3)*68+row] = vb.w;
        __syncthreads();
        #pragma unroll
        for (int k = 0; k < 16; k++) {
            float4 a4 = *(const float4*)(&As[k*68 + ty*4]);
            float4 b4 = *(const float4*)(&Bs[k*68 + tx*4]);
            float am[4] = {a4.x, a4.y, a4.z, a4.w};
            float bn[4] = {b4.x, b4.y, b4.z, b4.w};
            #pragma unroll
            for (int i = 0; i < 4; i++)
                #pragma unroll
                for (int j = 0; j < 4; j++) acc[i][j] += am[i]*bn[j];
        }
        __syncthreads();
    }
    #pragma unroll
    for (int i = 0; i < 4; i++) {
        int mm = m0 + ty*4 + i;
        #pragma unroll
        for (int j = 0; j < 4; j++) {
            int n = n0 + tx*4 + j;
            if (MODE == 0) {
                C[mm*768 + n] = acc[i][j] + bias[n];
            } else {
                float add = 0.0f;
                if (kz == 0) add = bias[n] + res[mm*768 + n];
                atomicAdd(&C[mm*768 + n], acc[i][j] + add);
            }
        }
    }
}

// ---------------- mma.sync fp16 GEMM, k32 slabs ------------------------------
#define TPITCH 80
#define TBYTES (128*TPITCH)
#define STAGEB (2*TBYTES)
#define NSTG 3
#define SMEMB (NSTG*STAGEB)          /* 61440 */
template<int MODE>
__global__ void __launch_bounds__(256, 2) gemm_mma(const float* __restrict__ bias,
                                                   float* __restrict__ Cout) {
    const int K  = (MODE == 0) ? 768 : KPAD;
    const int NS = K / 32;
    extern __shared__ __align__(1024) char sm[];
    uint32_t sb = s2u(sm);
    int tid = threadIdx.x;
    int w = tid >> 5, l = tid & 31;
    int wm = w >> 1, wn = w & 1;
    int b = blockIdx.z;
    int m0 = blockIdx.y * 128, n0 = blockIdx.x * 128;

    const __half* Ah = (MODE == 0) ? g_Wkvh : g_W2h;
    const __half* Bh = ((MODE == 0) ? g_nxTh : g_ich) + (size_t)b * NP * K;
    __half* Ch = g_kvh + (size_t)b * 2*CDIM*NP;
    float* Cf  = Cout + (size_t)b * CDIM*NP;

    float acc[2][8][4] = {};

    int r0 = tid >> 2, q0 = tid & 3;
    int r1 = ((tid + 256) >> 2), q1 = q0;

    auto load_stage = [&](int s) {
        uint32_t st = sb + (s % NSTG) * STAGEB;
        int k0 = s * 32;
        cp16(st + r0*TPITCH + q0*16,          Ah + (size_t)(m0+r0)*K + k0 + q0*8);
        cp16(st + r1*TPITCH + q1*16,          Ah + (size_t)(m0+r1)*K + k0 + q1*8);
        cp16(st + TBYTES + r0*TPITCH + q0*16, Bh + (size_t)(n0+r0)*K + k0 + q0*8);
        cp16(st + TBYTES + r1*TPITCH + q1*16, Bh + (size_t)(n0+r1)*K + k0 + q1*8);
        CP_COMMIT();
    };
    load_stage(0);
    load_stage(1);

    int lrow = (l & 7) + ((l >> 3) & 1) * 8;
    int lko  = (l >> 4) * 16;

    for (int s = 0; s < NS; s++) {
        if (s + 1 < NS) asm volatile("cp.async.wait_group 1;" ::: "memory");
        else            asm volatile("cp.async.wait_group 0;" ::: "memory");
        __syncthreads();
        if (s + 2 < NS) load_stage(s + 2);
        uint32_t st = sb + (s % NSTG) * STAGEB;
        #pragma unroll
        for (int kk = 0; kk < 2; kk++) {
            uint32_t aro = st + (wm*32 + lrow)*TPITCH + lko + kk*32;
            uint32_t bro = st + TBYTES + (wn*64 + lrow)*TPITCH + lko + kk*32;
            uint32_t ah[2][4], bf[4][4];
            #pragma unroll
            for (int mi = 0; mi < 2; mi++)
                LDSM_X4(ah[mi][0], ah[mi][1], ah[mi][2], ah[mi][3], aro + mi*16*TPITCH);
            #pragma unroll
            for (int np = 0; np < 4; np++)
                LDSM_X4(bf[np][0], bf[np][1], bf[np][2], bf[np][3], bro + np*16*TPITCH);
            #pragma unroll
            for (int mi = 0; mi < 2; mi++)
                #pragma unroll
                for (int ni = 0; ni < 8; ni++) {
                    int np = ni >> 1;
                    uint32_t b0r = (ni & 1) ? bf[np][1] : bf[np][0];
                    uint32_t b1r = (ni & 1) ? bf[np][3] : bf[np][2];
                    MMA16816(acc[mi][ni], ah[mi], b0r, b1r);
                }
        }
    }

    // epilogue
    #pragma unroll
    for (int mi = 0; mi < 2; mi++) {
        int rA = m0 + wm*32 + mi*16 + (l >> 2);
        int rB = rA + 8;
        float pA0, pA1, pB0, pB1;
        if (MODE == 0) { pA0 = bias[rA]; pA1 = 0.0f; pB0 = bias[rB]; pB1 = 0.0f; }
        else { pA0 = g_alpha[rA]; pA1 = g_beta[rA]; pB0 = g_alpha[rB]; pB1 = g_beta[rB]; }
        #pragma unroll
        for (int ni = 0; ni < 8; ni++) {
            int col = n0 + wn*64 + ni*8 + (l & 3)*2;
            float* c = acc[mi][ni];
            if (MODE == 0) {
                *(__half2*)(Ch + (size_t)rA*NP + col) = __floats2half2_rn(c[0]+pA0, c[1]+pA0);
                *(__half2*)(Ch + (size_t)rB*NP + col) = __floats2half2_rn(c[2]+pB0, c[3]+pB0);
            } else {
                *(float2*)(Cf + (size_t)rA*NP + col) =
                    make_float2(gelu_exact(c[0]*pA0 + pA1), gelu_exact(c[1]*pA0 + pA1));
                *(float2*)(Cf + (size_t)rB*NP + col) =
                    make_float2(gelu_exact(c[2]*pB0 + pB1), gelu_exact(c[3]*pB0 + pB1));
            }
        }
    }
}

// ---------------- fused attention, 128-wide chunks, m-split ------------------
// grid (8, NHEADS, BATCH), 256 threads: (n in 128) x (m-half in {0-9,10-19}).
__global__ void __launch_bounds__(256) k_attn() {
    int chunk = blockIdx.x, h = blockIdx.y, b = blockIdx.z;
    int tid = threadIdx.x, l = tid & 31;
    int nl = tid & 127, mh = (tid >> 7) * 10;
    __shared__ float qs[CLSN*DHEAD];
    __shared__ float ps[CLSN*128];
    __shared__ float bsum[CLSN];
    const float scale = 0.07216878364870322f;   // 1/sqrt(192)
    for (int i = tid; i < CLSN*DHEAD; i += 256) {
        int m = i / DHEAD, d = i - m*DHEAD;
        qs[i] = g_q[(b*CLSN + m)*CDIM + h*DHEAD + d] * scale;
    }
    if (tid < CLSN) bsum[tid] = 0.0f;
    __syncthreads();
    {
        int n = chunk*128 + nl;
        const __half* kvp = g_kvh + ((size_t)b*2*CDIM + h*DHEAD)*NP + n;
        float acc[10] = {};
        for (int d = 0; d < DHEAD; d++) {
            float kval = __half2float(kvp[(size_t)d * NP]);
            #pragma unroll
            for (int m = 0; m < 10; m++) acc[m] += qs[(mh + m)*DHEAD + d] * kval;
        }
        #pragma unroll
        for (int m = 0; m < 10; m++) {
            float e = __expf(acc[m]);
            ps[(mh + m)*128 + nl] = e;
            #pragma unroll
            for (int o = 16; o; o >>= 1) e += __shfl_xor_sync(0xFFFFFFFFu, e, o);
            if (l == 0) atomicAdd(&bsum[mh + m], e);
        }
    }
    __syncthreads();
    if (tid < CLSN)
        atomicAdd(&g_rowsum[((size_t)(b*NHEADS + h))*CLSN + tid], bsum[tid]);
    if (tid < DHEAD) {
        const __half* vp = g_kvh + ((size_t)b*2*CDIM + CDIM + h*DHEAD + tid)*NP + chunk*128;
        float acc[CLSN] = {};
        for (int nn = 0; nn < 128; nn += 2) {
            float2 vv = __half22float2(*(const __half2*)(vp + nn));
            #pragma unroll
            for (int m = 0; m < CLSN; m++)
                acc[m] += ps[m*128 + nn]*vv.x + ps[m*128 + nn + 1]*vv.y;
        }
        #pragma unroll
        for (int m = 0; m < CLSN; m++)
            atomicAdd(&g_outflat[(b*CLSN + m)*CDIM + h*DHEAD + tid], acc[m]);
    }
}

// ---------------- out_patch = out_cls @ input_patch, split-K x8 --------------
__global__ void __launch_bounds__(256) k_opatch(const float* __restrict__ patch,
                                                const float* __restrict__ ocls) {
    int chunk = blockIdx.x, b = blockIdx.y, kz = blockIdx.z;
    int tid = threadIdx.x;
    int n = chunk*256 + tid;
    __shared__ float a_s[CLSN*96];
    float acc[CLSN] = {};
    {
        int k0 = kz*96;
        for (int i = tid; i < CLSN*96; i += 256) {
            int m = i / 96, kk = i - m*96;
            a_s[i] = ocls[(b*CLSN + m)*CDIM + k0 + kk];
        }
        __syncthreads();
        for (int kk = 0; kk < 96; kk++) {
            float pv = patch[(size_t)b*PPB + (size_t)(k0+kk)*NP + n];
            #pragma unroll
            for (int m = 0; m < CLSN; m++) acc[m] += a_s[m*96 + kk] * pv;
        }
    }
    #pragma unroll
    for (int m = 0; m < CLSN; m++)
        atomicAdd(&g_opatch[((size_t)b*CLSN + m)*NP + n], acc[m]);
}

// ---------------- im2col transposed + fp16, 4-wide ---------------------------
__global__ void k_im2colT() {
    int i4 = blockIdx.x * 256 + threadIdx.x;
    int b = i4 / (NP*(KPAD/4));
    int rest = i4 - b * NP*(KPAD/4);
    int n = rest / (KPAD/4), kq = (rest - n*(KPAD/4)) * 4;
    int hh0 = n >> 5, ww0 = n & 31;
    __half vals[4];
    #pragma unroll
    for (int j = 0; j < 4; j++) {
        int k = kq + j;
        float val = 0.0f;
        if (k < 180) {
            int ic = k / 9, t = k - ic*9;
            int hh = hh0 + t/3 - 1, ww = ww0 + t%3 - 1;
            if (hh >= 0 && hh < 32 && ww >= 0 && ww < 32)
                val = g_opatch[((size_t)b*CLSN + ic)*NP + hh*32 + ww];
        }
        vals[j] = __float2half_rn(val);
    }
    *(uint2*)(g_ich + (size_t)i4*4) = *(uint2*)vals;
}

// ---------------- launcher ---------------------------------------------------
extern "C" void kernel_launch(void* const* d_in, const int* in_sizes, int n_in,
                              void* d_out, int out_size) {
    const float* x_cls  = (const float*)d_in[0];
    const float* patch  = (const float*)d_in[1];
    const float* ln_w   = (const float*)d_in[2];
    const float* ln_b   = (const float*)d_in[3];
    const float* nx_w   = (const float*)d_in[4];
    const float* nx_b   = (const float*)d_in[5];
    const float* Wq     = (const float*)d_in[6];
    const float* bq     = (const float*)d_in[7];
    const float* Wkv    = (const float*)d_in[8];
    const float* bkv    = (const float*)d_in[9];
    const float* Wp     = (const float*)d_in[10];
    const float* bp     = (const float*)d_in[11];
    const float* Wconv  = (const float*)d_in[12];
    const float* bconv  = (const float*)d_in[13];
    const float* bn_g   = (const float*)d_in[14];
    const float* bn_b   = (const float*)d_in[15];
    const float* bn_m   = (const float*)d_in[16];
    const float* bn_v   = (const float*)d_in[17];
    float* out_cls = (float*)d_out;
    float* y       = out_cls + ROWS*CDIM;

    static cudaStream_t s1 = nullptr, s2 = nullptr;
    static cudaEvent_t e0, e1, e2, e3, e4;
    if (!s1) {
        cudaStreamCreateWithFlags(&s1, cudaStreamNonBlocking);
        cudaStreamCreateWithFlags(&s2, cudaStreamNonBlocking);
        cudaEventCreateWithFlags(&e0, cudaEventDisableTiming);
        cudaEventCreateWithFlags(&e1, cudaEventDisableTiming);
        cudaEventCreateWithFlags(&e2, cudaEventDisableTiming);
        cudaEventCreateWithFlags(&e3, cudaEventDisableTiming);
        cudaEventCreateWithFlags(&e4, cudaEventDisableTiming);
        cudaFuncSetAttribute(gemm_mma<0>, cudaFuncAttributeMaxDynamicSharedMemorySize, SMEMB);
        cudaFuncSetAttribute(gemm_mma<1>, cudaFuncAttributeMaxDynamicSharedMemorySize, SMEMB);
    }
    cudaStream_t s0 = 0;

    // ---- minimal fork point ----
    k_zero_small<<<5, 256, 0, s0>>>();
    cudaEventRecord(e0, s0);

    // side chain 1: cls LN + q projection
    cudaStreamWaitEvent(s1, e0, 0);
    k_lncls<<<ROWS, 256, 0, s1>>>(x_cls, ln_w, ln_b);
    gemm_nt<0><<<dim3(12, 5), 256, 0, s1>>>(Wq, bq, nullptr, nullptr);
    cudaEventRecord(e1, s1);

    // side chain 2: bulk zero + weight preps
    cudaStreamWaitEvent(s2, e0, 0);
    k_zero_big<<<1280, 256, 0, s2>>>(out_cls);
    cudaEventRecord(e4, s2);
    k_prep_wkv<<<(2*CDIM*CDIM)/256, 256, 0, s2>>>(Wkv);
    cudaEventRecord(e2, s2);
    k_prepconv<<<(CDIM*KPAD + 255)/256, 256, 0, s2>>>(Wconv, bconv, bn_g, bn_b, bn_m, bn_v);
    cudaEventRecord(e3, s2);

    // main chain (critical path)
    k_psum<<<dim3(48, BATCH), 256, 0, s0>>>(patch);
    k_nxT<<<dim3(32, 12, BATCH), 256, 0, s0>>>(patch, nx_w, nx_b);
    cudaStreamWaitEvent(s0, e2, 0);
    gemm_mma<0><<<dim3(8, 12, BATCH), 256, SMEMB, s0>>>(bkv, nullptr);
    cudaStreamWaitEvent(s0, e1, 0);
    cudaStreamWaitEvent(s0, e4, 0);
    k_attn<<<dim3(8, NHEADS, BATCH), 256, 0, s0>>>();
    gemm_nt<1><<<dim3(12, 5, 8), 256, 0, s0>>>(Wp, bp, x_cls, out_cls);
    k_opatch<<<dim3(4, BATCH, 8), 256, 0, s0>>>(patch, out_cls);
    k_im2colT<<<(BATCH*NP*(KPAD/4))/256, 256, 0, s0>>>();
    cudaStreamWaitEvent(s0, e3, 0);
    gemm_mma<1><<<dim3(8, 6, BATCH), 256, SMEMB, s0>>>(nullptr, y);
}

// round 17
// speedup vs baseline: 1.2844x; 1.0709x over previous
#include <cuda_runtime.h>
#include <cuda_fp16.h>
#include <cstdint>
#include <math.h>

#define EPSV 1e-5f
#define BATCH 16
#define CLSN 20
#define CDIM 768
#define NHEADS 4
#define DHEAD 192
#define NP 1024
#define ROWS (BATCH*CLSN)
#define PPB (CDIM*NP)
#define KPAD 192

// ---------------- scratch ----------------------------------------------------
__device__ float g_xln[ROWS*CDIM];
__device__ float g_q[ROWS*CDIM];
__device__ float g_sums[32];
__device__ float g_rowsum[BATCH*NHEADS*CLSN];
__device__ float g_outflat[ROWS*CDIM];
__device__ float g_opatch[BATCH*CLSN*NP];
__device__ float g_alpha[CDIM];
__device__ float g_beta[CDIM];
__device__ __align__(128) __half g_kvh[BATCH*2*CDIM*NP];  // 50 MB fp16
__device__ __align__(128) __half g_Wkvh[2*CDIM*CDIM];
__device__ __align__(128) __half g_nxTh[BATCH*NP*CDIM];   // [b][n][c]
__device__ __align__(128) __half g_W2h[CDIM*KPAD];
__device__ __align__(128) __half g_ich[BATCH*NP*KPAD];    // [b][n][k]

__device__ __forceinline__ float gelu_exact(float x) {
    return 0.5f * x * (1.0f + erff(x * 0.70710678118654752440f));
}
__device__ __forceinline__ uint32_t s2u(const void* p) {
    uint32_t a;
    asm("{ .reg .u64 t; cvta.to.shared.u64 t, %1; cvt.u32.u64 %0, t; }" : "=r"(a) : "l"(p));
    return a;
}
__device__ __forceinline__ void cp16(uint32_t dst, const void* src) {
    asm volatile("cp.async.cg.shared.global [%0], [%1], 16;" :: "r"(dst), "l"(src));
}
#define CP_COMMIT() asm volatile("cp.async.commit_group;" ::: "memory")
#define LDSM_X4(r0,r1,r2,r3,a) \
    asm volatile("ldmatrix.sync.aligned.m8n8.x4.shared.b16 {%0,%1,%2,%3}, [%4];" \
                 : "=r"(r0), "=r"(r1), "=r"(r2), "=r"(r3) : "r"(a))
#define MMA16816(c, a, b0, b1) \
    asm volatile("mma.sync.aligned.m16n8k16.row.col.f32.f16.f16.f32 " \
                 "{%0,%1,%2,%3}, {%4,%5,%6,%7}, {%8,%9}, {%0,%1,%2,%3};" \
                 : "+f"((c)[0]), "+f"((c)[1]), "+f"((c)[2]), "+f"((c)[3]) \
                 : "r"((a)[0]), "r"((a)[1]), "r"((a)[2]), "r"((a)[3]), "r"(b0), "r"(b1))

// ---------------- zeroing ----------------------------------------------------
__global__ void k_zero_small() {
    int i = threadIdx.x + blockIdx.x * 256;
    if (i < 32) g_sums[i] = 0.0f;
    if (i < BATCH*NHEADS*CLSN) g_rowsum[i] = 0.0f;
}
__global__ void k_zero_big(float* __restrict__ out_cls) {
    int i = blockIdx.x * 256 + threadIdx.x;
    if (i < ROWS*CDIM) { g_outflat[i] = 0.0f; out_cls[i] = 0.0f; }
    if (i < BATCH*CLSN*NP) g_opatch[i] = 0.0f;
}

__global__ void k_lncls(const float* __restrict__ x, const float* __restrict__ w,
                        const float* __restrict__ bb) {
    int r = blockIdx.x, tid = threadIdx.x;
    const float* xr = x + r * CDIM;
    float v0 = xr[tid], v1 = xr[tid+256], v2 = xr[tid+512];
    __shared__ float red[256];
    __shared__ float s_mu, s_rs;
    red[tid] = v0 + v1 + v2; __syncthreads();
    for (int o = 128; o; o >>= 1) { if (tid < o) red[tid] += red[tid+o]; __syncthreads(); }
    if (tid == 0) s_mu = red[0] * (1.0f/768.0f);
    __syncthreads();
    float mu = s_mu;
    float d0 = v0-mu, d1 = v1-mu, d2 = v2-mu;
    red[tid] = d0*d0 + d1*d1 + d2*d2; __syncthreads();
    for (int o = 128; o; o >>= 1) { if (tid < o) red[tid] += red[tid+o]; __syncthreads(); }
    if (tid == 0) s_rs = rsqrtf(red[0] * (1.0f/768.0f) + EPSV);
    __syncthreads();
    float rs = s_rs;
    float* o = g_xln + r * CDIM;
    o[tid]     = d0*rs*w[tid]     + bb[tid];
    o[tid+256] = d1*rs*w[tid+256] + bb[tid+256];
    o[tid+512] = d2*rs*w[tid+512] + bb[tid+512];
}

// vectorized per-batch sums
__global__ void k_psum(const float* __restrict__ x) {
    int b = blockIdx.y, tid = threadIdx.x;
    const float4* p = (const float4*)(x + (size_t)b * PPB + blockIdx.x * 16384);
    float s = 0.0f, q = 0.0f;
    #pragma unroll 4
    for (int i = 0; i < 16; i++) {
        float4 v = p[i*256 + tid];
        s += v.x + v.y + v.z + v.w;
        q += v.x*v.x + v.y*v.y + v.z*v.z + v.w*v.w;
    }
    __shared__ float rs[256], rq[256];
    rs[tid] = s; rq[tid] = q; __syncthreads();
    for (int o = 128; o; o >>= 1) {
        if (tid < o) { rs[tid] += rs[tid+o]; rq[tid] += rq[tid+o]; }
        __syncthreads();
    }
    if (tid == 0) { atomicAdd(&g_sums[b], rs[0]); atomicAdd(&g_sums[16+b], rq[0]); }
}

// normalize + transpose + fp16:  g_nxTh[b][n][c].  32n x 64c tiles, half2 out.
__global__ void __launch_bounds__(256) k_nxT(const float* __restrict__ x,
                                             const float* __restrict__ w,
                                             const float* __restrict__ bb) {
    __shared__ float t[32][72];
    int b = blockIdx.z, c0 = blockIdx.y*64, n0 = blockIdx.x*32;
    int tx = threadIdx.x & 31, ty = threadIdx.x >> 5;
    float mu  = g_sums[b]    * (1.0f/786432.0f);
    float var = g_sums[16+b] * (1.0f/786432.0f) - mu*mu;
    float rv = rsqrtf(var + EPSV);
    #pragma unroll
    for (int i = 0; i < 8; i++) {
        int c = c0 + ty + i*8;
        float v = x[(size_t)b*PPB + (size_t)c*NP + n0 + tx];
        t[tx][ty + i*8] = (v - mu)*rv*w[c] + bb[c];
    }
    __syncthreads();
    #pragma unroll
    for (int i = 0; i < 4; i++) {
        int n = n0 + ty + i*8;
        float v0 = t[ty + i*8][tx*2], v1 = t[ty + i*8][tx*2 + 1];
        *(__half2*)(g_nxTh + ((size_t)b*NP + n)*CDIM + c0 + tx*2) =
            __floats2half2_rn(v0, v1);
    }
}

__global__ void k_prep_wkv(const float* __restrict__ W) {
    int i = blockIdx.x * 256 + threadIdx.x;
    if (i < 2*CDIM*CDIM) g_Wkvh[i] = __float2half_rn(W[i]);
}

__global__ void k_prepconv(const float* __restrict__ Wc, const float* __restrict__ bc,
                           const float* __restrict__ g,  const float* __restrict__ bt,
                           const float* __restrict__ mn, const float* __restrict__ vr) {
    int i = blockIdx.x * 256 + threadIdx.x;
    if (i < CDIM*KPAD) {
        int o = i / KPAD, k = i - o*KPAD;
        g_W2h[i] = __float2half_rn((k < 180) ? Wc[o*180 + k] : 0.0f);
    }
    if (i < CDIM) {
        float al = g[i] * rsqrtf(vr[i] + EPSV);
        g_alpha[i] = al;
        g_beta[i]  = (bc[i] - mn[i]) * al + bt[i];
    }
}

// ---------------- small NT GEMM --------------------------------------------
template<int MODE>
__global__ void __launch_bounds__(256) gemm_nt(const float* __restrict__ Bw,
                                               const float* __restrict__ bias,
                                               const float* __restrict__ res,
                                               float* __restrict__ Cext) {
    const float* A = (MODE == 0) ? g_xln : g_outflat;
    float* C = (MODE == 0) ? g_q : Cext;
    __shared__ float As[16*68];
    __shared__ float Bs[16*68];
    int m0 = blockIdx.y * 64, n0 = blockIdx.x * 64, kz = (MODE == 0) ? 0 : blockIdx.z;
    const int KB = (MODE == 0) ? 768 : 96;
    int tid = threadIdx.x, tx = tid & 15, ty = tid >> 4;
    float acc[4][4] = {};
    int row = tid >> 2, kq = tid & 3;
    int m = m0 + row;
    int bb_ = m / CLSN, mc = m - bb_*CLSN;
    for (int k0 = kz*96; k0 < kz*96 + KB; k0 += 16) {
        float4 va = *(const float4*)(A  + (size_t)m*768 + k0 + kq*4);
        float4 vb = *(const float4*)(Bw + (size_t)(n0+row)*768 + k0 + kq*4);
        if (MODE == 1) {
            int h = (k0 + kq*4) / DHEAD;
            float inv = 1.0f / g_rowsum[((size_t)(bb_*NHEADS + h))*CLSN + mc];
            va.x *= inv; va.y *= inv; va.z *= inv; va.w *= inv;
        }
        As[(kq*4+0)*68+row] = va.x; As[(kq*4+1)*68+row] = va.y;
        As[(kq*4+2)*68+row] = va.z; As[(kq*4+3)*68+row] = va.w;
        Bs[(kq*4+0)*68+row] = vb.x; Bs[(kq*4+1)*68+row] = vb.y;
        Bs[(kq*4+2)*68+row] = vb.z; Bs[(kq*4+3)*68+row] = vb.w;
        __syncthreads();
        #pragma unroll
        for (int k = 0; k < 16; k++) {
            float4 a4 = *(const float4*)(&As[k*68 + ty*4]);
            float4 b4 = *(const float4*)(&Bs[k*68 + tx*4]);
            float am[4] = {a4.x, a4.y, a4.z, a4.w};
            float bn[4] = {b4.x, b4.y, b4.z, b4.w};
            #pragma unroll
            for (int i = 0; i < 4; i++)
                #pragma unroll
                for (int j = 0; j < 4; j++) acc[i][j] += am[i]*bn[j];
        }
        __syncthreads();
    }
    #pragma unroll
    for (int i = 0; i < 4; i++) {
        int mm = m0 + ty*4 + i;
        #pragma unroll
        for (int j = 0; j < 4; j++) {
            int n = n0 + tx*4 + j;
            if (MODE == 0) {
                C[mm*768 + n] = acc[i][j] + bias[n];
            } else {
                float add = 0.0f;
                if (kz == 0) add = bias[n] + res[mm*768 + n];
                atomicAdd(&C[mm*768 + n], acc[i][j] + add);
            }
        }
    }
}

// ---------------- mma.sync fp16 GEMM, k32 slabs, 4-stage pipeline ------------
#define TPITCH 80
#define TBYTES (128*TPITCH)
#define STAGEB (2*TBYTES)
#define NSTG 4
#define SMEMB (NSTG*STAGEB)          /* 81920 */
template<int MODE>
__global__ void __launch_bounds__(256, 2) gemm_mma(const float* __restrict__ bias,
                                                   float* __restrict__ Cout) {
    const int K  = (MODE == 0) ? 768 : KPAD;
    const int NS = K / 32;
    extern __shared__ __align__(1024) char sm[];
    uint32_t sb = s2u(sm);
    int tid = threadIdx.x;
    int w = tid >> 5, l = tid & 31;
    int wm = w >> 1, wn = w & 1;
    int b = blockIdx.z;
    int m0 = blockIdx.y * 128, n0 = blockIdx.x * 128;

    const __half* Ah = (MODE == 0) ? g_Wkvh : g_W2h;
    const __half* Bh = ((MODE == 0) ? g_nxTh : g_ich) + (size_t)b * NP * K;
    __half* Ch = g_kvh + (size_t)b * 2*CDIM*NP;
    float* Cf  = Cout + (size_t)b * CDIM*NP;

    float acc[2][8][4] = {};

    int r0 = tid >> 2, q0 = tid & 3;
    int r1 = ((tid + 256) >> 2), q1 = q0;

    auto load_stage = [&](int s) {
        uint32_t st = sb + (s % NSTG) * STAGEB;
        int k0 = s * 32;
        cp16(st + r0*TPITCH + q0*16,          Ah + (size_t)(m0+r0)*K + k0 + q0*8);
        cp16(st + r1*TPITCH + q1*16,          Ah + (size_t)(m0+r1)*K + k0 + q1*8);
        cp16(st + TBYTES + r0*TPITCH + q0*16, Bh + (size_t)(n0+r0)*K + k0 + q0*8);
        cp16(st + TBYTES + r1*TPITCH + q1*16, Bh + (size_t)(n0+r1)*K + k0 + q1*8);
        CP_COMMIT();
    };
    load_stage(0);
    load_stage(1);
    load_stage(2);

    int lrow = (l & 7) + ((l >> 3) & 1) * 8;
    int lko  = (l >> 4) * 16;

    for (int s = 0; s < NS; s++) {
        if (s + 3 <= NS)      asm volatile("cp.async.wait_group 2;" ::: "memory");
        else if (s + 2 == NS) asm volatile("cp.async.wait_group 1;" ::: "memory");
        else                  asm volatile("cp.async.wait_group 0;" ::: "memory");
        __syncthreads();
        if (s + 3 < NS) load_stage(s + 3);
        uint32_t st = sb + (s % NSTG) * STAGEB;
        #pragma unroll
        for (int kk = 0; kk < 2; kk++) {
            uint32_t aro = st + (wm*32 + lrow)*TPITCH + lko + kk*32;
            uint32_t bro = st + TBYTES + (wn*64 + lrow)*TPITCH + lko + kk*32;
            uint32_t ah[2][4], bf[4][4];
            #pragma unroll
            for (int mi = 0; mi < 2; mi++)
                LDSM_X4(ah[mi][0], ah[mi][1], ah[mi][2], ah[mi][3], aro + mi*16*TPITCH);
            #pragma unroll
            for (int np = 0; np < 4; np++)
                LDSM_X4(bf[np][0], bf[np][1], bf[np][2], bf[np][3], bro + np*16*TPITCH);
            #pragma unroll
            for (int mi = 0; mi < 2; mi++)
                #pragma unroll
                for (int ni = 0; ni < 8; ni++) {
                    int np = ni >> 1;
                    uint32_t b0r = (ni & 1) ? bf[np][1] : bf[np][0];
                    uint32_t b1r = (ni & 1) ? bf[np][3] : bf[np][2];
                    MMA16816(acc[mi][ni], ah[mi], b0r, b1r);
                }
        }
    }

    // epilogue
    #pragma unroll
    for (int mi = 0; mi < 2; mi++) {
        int rA = m0 + wm*32 + mi*16 + (l >> 2);
        int rB = rA + 8;
        float pA0, pA1, pB0, pB1;
        if (MODE == 0) { pA0 = bias[rA]; pA1 = 0.0f; pB0 = bias[rB]; pB1 = 0.0f; }
        else { pA0 = g_alpha[rA]; pA1 = g_beta[rA]; pB0 = g_alpha[rB]; pB1 = g_beta[rB]; }
        #pragma unroll
        for (int ni = 0; ni < 8; ni++) {
            int col = n0 + wn*64 + ni*8 + (l & 3)*2;
            float* c = acc[mi][ni];
            if (MODE == 0) {
                *(__half2*)(Ch + (size_t)rA*NP + col) = __floats2half2_rn(c[0]+pA0, c[1]+pA0);
                *(__half2*)(Ch + (size_t)rB*NP + col) = __floats2half2_rn(c[2]+pB0, c[3]+pB0);
            } else {
                *(float2*)(Cf + (size_t)rA*NP + col) =
                    make_float2(gelu_exact(c[0]*pA0 + pA1), gelu_exact(c[1]*pA0 + pA1));
                *(float2*)(Cf + (size_t)rB*NP + col) =
                    make_float2(gelu_exact(c[2]*pB0 + pB1), gelu_exact(c[3]*pB0 + pB1));
            }
        }
    }
}

// ---------------- fused attention, 128-wide chunks, m-split ------------------
__global__ void __launch_bounds__(256) k_attn() {
    int chunk = blockIdx.x, h = blockIdx.y, b = blockIdx.z;
    int tid = threadIdx.x, l = tid & 31;
    int nl = tid & 127, mh = (tid >> 7) * 10;
    __shared__ float qs[CLSN*DHEAD];
    __shared__ float ps[CLSN*128];
    __shared__ float bsum[CLSN];
    const float scale = 0.07216878364870322f;   // 1/sqrt(192)
    for (int i = tid; i < CLSN*DHEAD; i += 256) {
        int m = i / DHEAD, d = i - m*DHEAD;
        qs[i] = g_q[(b*CLSN + m)*CDIM + h*DHEAD + d] * scale;
    }
    if (tid < CLSN) bsum[tid] = 0.0f;
    __syncthreads();
    {
        int n = chunk*128 + nl;
        const __half* kvp = g_kvh + ((size_t)b*2*CDIM + h*DHEAD)*NP + n;
        float acc[10] = {};
        #pragma unroll 8
        for (int d = 0; d < DHEAD; d++) {
            float kval = __half2float(kvp[(size_t)d * NP]);
            #pragma unroll
            for (int m = 0; m < 10; m++) acc[m] += qs[(mh + m)*DHEAD + d] * kval;
        }
        #pragma unroll
        for (int m = 0; m < 10; m++) {
            float e = __expf(acc[m]);
            ps[(mh + m)*128 + nl] = e;
            #pragma unroll
            for (int o = 16; o; o >>= 1) e += __shfl_xor_sync(0xFFFFFFFFu, e, o);
            if (l == 0) atomicAdd(&bsum[mh + m], e);
        }
    }
    __syncthreads();
    if (tid < CLSN)
        atomicAdd(&g_rowsum[((size_t)(b*NHEADS + h))*CLSN + tid], bsum[tid]);
    if (tid < DHEAD) {
        const __half* vp = g_kvh + ((size_t)b*2*CDIM + CDIM + h*DHEAD + tid)*NP + chunk*128;
        float acc[CLSN] = {};
        #pragma unroll 4
        for (int nn = 0; nn < 128; nn += 2) {
            float2 vv = __half22float2(*(const __half2*)(vp + nn));
            #pragma unroll
            for (int m = 0; m < CLSN; m++)
                acc[m] += ps[m*128 + nn]*vv.x + ps[m*128 + nn + 1]*vv.y;
        }
        #pragma unroll
        for (int m = 0; m < CLSN; m++)
            atomicAdd(&g_outflat[(b*CLSN + m)*CDIM + h*DHEAD + tid], acc[m]);
    }
}

// ---------------- out_patch = out_cls @ input_patch, split-K x8 --------------
__global__ void __launch_bounds__(256) k_opatch(const float* __restrict__ patch,
                                                const float* __restrict__ ocls) {
    int chunk = blockIdx.x, b = blockIdx.y, kz = blockIdx.z;
    int tid = threadIdx.x;
    int n = chunk*256 + tid;
    __shared__ float a_s[CLSN*96];
    float acc[CLSN] = {};
    {
        int k0 = kz*96;
        for (int i = tid; i < CLSN*96; i += 256) {
            int m = i / 96, kk = i - m*96;
            a_s[i] = ocls[(b*CLSN + m)*CDIM + k0 + kk];
        }
        __syncthreads();
        for (int kk = 0; kk < 96; kk++) {
            float pv = patch[(size_t)b*PPB + (size_t)(k0+kk)*NP + n];
            #pragma unroll
            for (int m = 0; m < CLSN; m++) acc[m] += a_s[m*96 + kk] * pv;
        }
    }
    #pragma unroll
    for (int m = 0; m < CLSN; m++)
        atomicAdd(&g_opatch[((size_t)b*CLSN + m)*NP + n], acc[m]);
}

// ---------------- im2col transposed + fp16, 4-wide ---------------------------
__global__ void k_im2colT() {
    int i4 = blockIdx.x * 256 + threadIdx.x;
    int b = i4 / (NP*(KPAD/4));
    int rest = i4 - b * NP*(KPAD/4);
    int n = rest / (KPAD/4), kq = (rest - n*(KPAD/4)) * 4;
    int hh0 = n >> 5, ww0 = n & 31;
    __half vals[4];
    #pragma unroll
    for (int j = 0; j < 4; j++) {
        int k = kq + j;
        float val = 0.0f;
        if (k < 180) {
            int ic = k / 9, t = k - ic*9;
            int hh = hh0 + t/3 - 1, ww = ww0 + t%3 - 1;
            if (hh >= 0 && hh < 32 && ww >= 0 && ww < 32)
                val = g_opatch[((size_t)b*CLSN + ic)*NP + hh*32 + ww];
        }
        vals[j] = __float2half_rn(val);
    }
    *(uint2*)(g_ich + (size_t)i4*4) = *(uint2*)vals;
}

// ---------------- launcher ---------------------------------------------------
extern "C" void kernel_launch(void* const* d_in, const int* in_sizes, int n_in,
                              void* d_out, int out_size) {
    const float* x_cls  = (const float*)d_in[0];
    const float* patch  = (const float*)d_in[1];
    const float* ln_w   = (const float*)d_in[2];
    const float* ln_b   = (const float*)d_in[3];
    const float* nx_w   = (const float*)d_in[4];
    const float* nx_b   = (const float*)d_in[5];
    const float* Wq     = (const float*)d_in[6];
    const float* bq     = (const float*)d_in[7];
    const float* Wkv    = (const float*)d_in[8];
    const float* bkv    = (const float*)d_in[9];
    const float* Wp     = (const float*)d_in[10];
    const float* bp     = (const float*)d_in[11];
    const float* Wconv  = (const float*)d_in[12];
    const float* bconv  = (const float*)d_in[13];
    const float* bn_g   = (const float*)d_in[14];
    const float* bn_b   = (const float*)d_in[15];
    const float* bn_m   = (const float*)d_in[16];
    const float* bn_v   = (const float*)d_in[17];
    float* out_cls = (float*)d_out;
    float* y       = out_cls + ROWS*CDIM;

    static cudaStream_t s1 = nullptr, s2 = nullptr;
    static cudaEvent_t e0, e1, e2, e3, e4;
    if (!s1) {
        cudaStreamCreateWithFlags(&s1, cudaStreamNonBlocking);
        cudaStreamCreateWithFlags(&s2, cudaStreamNonBlocking);
        cudaEventCreateWithFlags(&e0, cudaEventDisableTiming);
        cudaEventCreateWithFlags(&e1, cudaEventDisableTiming);
        cudaEventCreateWithFlags(&e2, cudaEventDisableTiming);
        cudaEventCreateWithFlags(&e3, cudaEventDisableTiming);
        cudaEventCreateWithFlags(&e4, cudaEventDisableTiming);
        cudaFuncSetAttribute(gemm_mma<0>, cudaFuncAttributeMaxDynamicSharedMemorySize, SMEMB);
        cudaFuncSetAttribute(gemm_mma<1>, cudaFuncAttributeMaxDynamicSharedMemorySize, SMEMB);
    }
    cudaStream_t s0 = 0;

    // ---- minimal fork point ----
    k_zero_small<<<5, 256, 0, s0>>>();
    cudaEventRecord(e0, s0);

    // side chain 1: cls LN + q projection
    cudaStreamWaitEvent(s1, e0, 0);
    k_lncls<<<ROWS, 256, 0, s1>>>(x_cls, ln_w, ln_b);
    gemm_nt<0><<<dim3(12, 5), 256, 0, s1>>>(Wq, bq, nullptr, nullptr);
    cudaEventRecord(e1, s1);

    // side chain 2: bulk zero + weight preps
    cudaStreamWaitEvent(s2, e0, 0);
    k_zero_big<<<1280, 256, 0, s2>>>(out_cls);
    cudaEventRecord(e4, s2);
    k_prep_wkv<<<(2*CDIM*CDIM)/256, 256, 0, s2>>>(Wkv);
    cudaEventRecord(e2, s2);
    k_prepconv<<<(CDIM*KPAD + 255)/256, 256, 0, s2>>>(Wconv, bconv, bn_g, bn_b, bn_m, bn_v);
    cudaEventRecord(e3, s2);

    // main chain (critical path)
    k_psum<<<dim3(48, BATCH), 256, 0, s0>>>(patch);
    k_nxT<<<dim3(32, 12, BATCH), 256, 0, s0>>>(patch, nx_w, nx_b);
    cudaStreamWaitEvent(s0, e2, 0);
    gemm_mma<0><<<dim3(8, 12, BATCH), 256, SMEMB, s0>>>(bkv, nullptr);
    cudaStreamWaitEvent(s0, e1, 0);
    cudaStreamWaitEvent(s0, e4, 0);
    k_attn<<<dim3(8, NHEADS, BATCH), 256, 0, s0>>>();
    gemm_nt<1><<<dim3(12, 5, 8), 256, 0, s0>>>(Wp, bp, x_cls, out_cls);
    k_opatch<<<dim3(4, BATCH, 8), 256, 0, s0>>>(patch, out_cls);
    k_im2colT<<<(BATCH*NP*(KPAD/4))/256, 256, 0, s0>>>();
    cudaStreamWaitEvent(s0, e3, 0);
    gemm_mma<1><<<dim3(8, 6, BATCH), 256, SMEMB, s0>>>(nullptr, y);
}